// round 5
// baseline (speedup 1.0000x reference)
#include <cuda_runtime.h>
#include <cuda_bf16.h>
#include <math.h>
#include <stdint.h>

// ---------------- problem constants ----------------
#define T_TOK   2048
#define D_MODEL 1280
#define H_HEADS 16
#define HD      80
#define HALF    40
#define FF_DIM  3420
#define FF_PAD  3456
#define DEPTH   4
#define OUT_DIM 3584
#define PATCH_IN 1176
#define PATCH_KP 1216
#define WIN     64
#define NWIN    (T_TOK / WIN)
#define EPS_RMS 1e-6f
#define ATT_SCALE 0.1118033988749895f

// ---------------- helpers ----------------
__device__ __forceinline__ uint32_t smem_u32(const void* p) {
    uint32_t a;
    asm("{ .reg .u64 t; cvta.to.shared.u64 t, %1; cvt.u32.u64 %0, t; }" : "=r"(a) : "l"(p));
    return a;
}
__device__ __forceinline__ void cp_async16(uint32_t s, const void* g) {
    asm volatile("cp.async.cg.shared.global [%0], [%1], 16;" :: "r"(s), "l"(g));
}
#define CP_COMMIT() asm volatile("cp.async.commit_group;" ::: "memory")
#define CP_WAIT(n)  asm volatile("cp.async.wait_group %0;" :: "n"(n) : "memory")

__device__ __forceinline__ void ldm_x4(uint32_t& r0, uint32_t& r1, uint32_t& r2,
                                       uint32_t& r3, uint32_t addr) {
    asm volatile("ldmatrix.sync.aligned.m8n8.x4.shared.b16 {%0,%1,%2,%3}, [%4];"
                 : "=r"(r0), "=r"(r1), "=r"(r2), "=r"(r3) : "r"(addr));
}
__device__ __forceinline__ void imma16832(int* d, const uint32_t* a,
                                          uint32_t b0, uint32_t b1) {
    asm volatile("mma.sync.aligned.m16n8k32.row.col.s32.s8.s8.s32 "
                 "{%0,%1,%2,%3}, {%4,%5,%6,%7}, {%8,%9}, {%0,%1,%2,%3};"
                 : "+r"(d[0]), "+r"(d[1]), "+r"(d[2]), "+r"(d[3])
                 : "r"(a[0]), "r"(a[1]), "r"(a[2]), "r"(a[3]), "r"(b0), "r"(b1));
}

__device__ __forceinline__ int8_t q8(float v) {
    return (int8_t)__float2int_rn(fminf(fmaxf(v, -127.f), 127.f));
}

// ---------------- scratch: fp32 streams ----------------
__device__ float g_h    [T_TOK * D_MODEL];
__device__ float g_qkv  [T_TOK * 3 * D_MODEL];
__device__ float g_att  [T_TOK * D_MODEL];
__device__ float g_gatef[(size_t)T_TOK * FF_DIM];
__device__ float g_upf  [(size_t)T_TOK * FF_DIM];
__device__ float g_f1f  [512 * 4 * D_MODEL];

// ---------------- int8 activation planes + row scales ----------------
__device__ int8_t g_x1 [T_TOK * PATCH_KP], g_x2 [T_TOK * PATCH_KP];
__device__ int8_t g_n1 [T_TOK * D_MODEL],  g_n2 [T_TOK * D_MODEL];
__device__ int8_t g_at1[T_TOK * D_MODEL],  g_at2[T_TOK * D_MODEL];
__device__ int8_t g_up1[(size_t)T_TOK * FF_PAD], g_up2[(size_t)T_TOK * FF_PAD];
__device__ int8_t g_f11[512 * 4 * D_MODEL], g_f12[512 * 4 * D_MODEL];
__device__ float  g_xq[T_TOK], g_nq[T_TOK], g_atq[T_TOK], g_upq[T_TOK], g_f1q[512];

// ---------------- int8 weight planes [N, Kp] + per-col scales ----------------
__device__ int8_t g_patchW1[1280 * PATCH_KP],               g_patchW2[1280 * PATCH_KP];
__device__ int8_t g_qkvW1 [DEPTH * 3840 * 1280],            g_qkvW2 [DEPTH * 3840 * 1280];
__device__ int8_t g_projW1[DEPTH * 1280 * 1280],            g_projW2[DEPTH * 1280 * 1280];
__device__ int8_t g_gateW1[(size_t)DEPTH * FF_PAD * 1280],  g_gateW2[(size_t)DEPTH * FF_PAD * 1280];
__device__ int8_t g_upW1  [(size_t)DEPTH * FF_PAD * 1280],  g_upW2  [(size_t)DEPTH * FF_PAD * 1280];
__device__ int8_t g_downW1[(size_t)DEPTH * 1280 * FF_PAD],  g_downW2[(size_t)DEPTH * 1280 * FF_PAD];
__device__ int8_t g_fc1W1 [5120 * 5120],                    g_fc1W2 [5120 * 5120];
__device__ int8_t g_fc2W1 [3584 * 5120],                    g_fc2W2 [3584 * 5120];
__device__ float  g_wscale[65536];

// ---------------- weight col-max (pass 1) ----------------
#define NSEG 23
struct MSeg { const float* src; int K, N, Np, sbase, blk0; };
struct MTable { MSeg seg[NSEG]; };

__global__ void colmax_all(MTable tb) {
    const int blk = blockIdx.x;
    int si = 0;
#pragma unroll
    for (int i = 1; i < NSEG; i++) si += (tb.seg[i].blk0 <= blk);
    const MSeg sg = tb.seg[si];
    const int n = (blk - sg.blk0) * 256 + threadIdx.x;
    if (n >= sg.Np) return;
    float m = 0.f;
    if (n < sg.N) {
        const float* p = sg.src + n;
#pragma unroll 4
        for (int k = 0; k < sg.K; k++) m = fmaxf(m, fabsf(p[(size_t)k * sg.N]));
    }
    g_wscale[sg.sbase + n] = m * (1.f / 127.f);
}

// ---------------- weight transpose + 2-digit quantize (pass 2) ----------------
struct QSeg { const float* s; int8_t* d1; int8_t* d2; int K, N, Kp, sbase, tile0, tilesX; };
struct QTable { QSeg seg[NSEG]; };

__global__ void conv_all(QTable tb) {
    __shared__ float t[32][33];
    const int tile = blockIdx.x;
    int si = 0;
#pragma unroll
    for (int i = 1; i < NSEG; i++) si += (tb.seg[i].tile0 <= tile);
    const QSeg sg = tb.seg[si];
    const int lt = tile - sg.tile0;
    const int kb = (lt % sg.tilesX) * 32;
    const int nb = (lt / sg.tilesX) * 32;
#pragma unroll
    for (int j = 0; j < 32; j += 8) {
        int k = kb + threadIdx.y + j, n = nb + threadIdx.x;
        t[threadIdx.y + j][threadIdx.x] =
            (k < sg.K && n < sg.N) ? sg.s[(size_t)k * sg.N + n] : 0.f;
    }
    __syncthreads();
#pragma unroll
    for (int j = 0; j < 32; j += 8) {
        const int n = nb + threadIdx.y + j, k = kb + threadIdx.x;
        const float s = g_wscale[sg.sbase + n];
        const float inv = (s > 0.f) ? 1.f / s : 0.f;
        const float v = t[threadIdx.x][threadIdx.y + j] * inv;
        const float d1 = rintf(v);
        sg.d1[(size_t)n * sg.Kp + k] = (int8_t)(int)d1;
        sg.d2[(size_t)n * sg.Kp + k] = q8((v - d1) * 256.f);
    }
}

// ---------------- per-row activation quantize ----------------
__global__ void quant_rows(const float* __restrict__ X, int8_t* __restrict__ Q1,
                           int8_t* __restrict__ Q2, float* __restrict__ sq,
                           int N, int Np, int strideX)
{
    const int row = blockIdx.x;
    const float* xr = X + (size_t)row * strideX;
    float m = 0.f;
    for (int i = threadIdx.x; i < N; i += 256) m = fmaxf(m, fabsf(xr[i]));
#pragma unroll
    for (int o = 16; o; o >>= 1) m = fmaxf(m, __shfl_xor_sync(~0u, m, o));
    __shared__ float red[8];
    const int warp = threadIdx.x >> 5, lane = threadIdx.x & 31;
    if (lane == 0) red[warp] = m;
    __syncthreads();
    if (warp == 0) {
        float v = (lane < 8) ? red[lane] : 0.f;
#pragma unroll
        for (int o = 4; o; o >>= 1) v = fmaxf(v, __shfl_xor_sync(~0u, v, o));
        if (lane == 0) red[0] = v;
    }
    __syncthreads();
    m = red[0];
    const float inv = (m > 0.f) ? 127.f / m : 0.f;
    if (threadIdx.x == 0) sq[row] = m * (1.f / 127.f);
    int8_t* q1 = Q1 + (size_t)row * Np;
    int8_t* q2 = Q2 + (size_t)row * Np;
    for (int i = threadIdx.x; i < Np; i += 256) {
        const float v = (i < N) ? xr[i] * inv : 0.f;
        const float d1 = rintf(v);
        q1[i] = (int8_t)(int)d1;
        q2[i] = q8((v - d1) * 256.f);
    }
}

// ---------------- rmsnorm + quantize ----------------
__global__ void rmsnorm_quant(const float* __restrict__ x, const float* __restrict__ s,
                              int8_t* __restrict__ Q1, int8_t* __restrict__ Q2,
                              float* __restrict__ sq)
{
    const int row = blockIdx.x;
    const float* xr = x + (size_t)row * D_MODEL;
    float sum = 0.f, m = 0.f;
    for (int i = threadIdx.x; i < D_MODEL; i += 256) {
        const float v = xr[i];
        sum += v * v;
        m = fmaxf(m, fabsf(v * s[i]));
    }
#pragma unroll
    for (int o = 16; o; o >>= 1) {
        sum += __shfl_xor_sync(~0u, sum, o);
        m = fmaxf(m, __shfl_xor_sync(~0u, m, o));
    }
    __shared__ float redS[8], redM[8];
    const int warp = threadIdx.x >> 5, lane = threadIdx.x & 31;
    if (lane == 0) { redS[warp] = sum; redM[warp] = m; }
    __syncthreads();
    if (warp == 0) {
        float v = (lane < 8) ? redS[lane] : 0.f;
        float w = (lane < 8) ? redM[lane] : 0.f;
#pragma unroll
        for (int o = 4; o; o >>= 1) {
            v += __shfl_xor_sync(~0u, v, o);
            w = fmaxf(w, __shfl_xor_sync(~0u, w, o));
        }
        if (lane == 0) { redS[0] = v; redM[0] = w; }
    }
    __syncthreads();
    const float rinv = rsqrtf(redS[0] * (1.f / D_MODEL) + EPS_RMS);
    const float vmax = redM[0] * rinv;
    const float inv = (vmax > 0.f) ? 127.f / vmax : 0.f;
    if (threadIdx.x == 0) sq[row] = vmax * (1.f / 127.f);
    int8_t* q1 = Q1 + (size_t)row * D_MODEL;
    int8_t* q2 = Q2 + (size_t)row * D_MODEL;
    for (int i = threadIdx.x; i < D_MODEL; i += 256) {
        const float v = xr[i] * s[i] * rinv * inv;
        const float d1 = rintf(v);
        q1[i] = (int8_t)(int)d1;
        q2[i] = q8((v - d1) * 256.f);
    }
}

// ---------------- int8 GEMM, 3 digit-passes, fused epilogue ----------------
enum { EPI_NONE = 0, EPI_BIAS, EPI_BIAS_SILU, EPI_BIAS_RES, EPI_BIAS_MUL, EPI_BIAS_GELU };

#define ROWP 80
#define STAGE_BYTES (2 * 128 * ROWP)
#define NSTAGE 4
#define GEMM_SMEM (NSTAGE * STAGE_BYTES)

template <int EPI>
__global__ __launch_bounds__(256, 1)
void gemm_i8(const int8_t* __restrict__ A1, const int8_t* __restrict__ A2,
             const int8_t* __restrict__ B1, const int8_t* __restrict__ B2,
             const float* __restrict__ saA, const float* __restrict__ sbB,
             const float* __restrict__ bias, const float* __restrict__ Rsrc,
             float* __restrict__ C, int Kp, int Nlog, int Nstride, int Rstride)
{
    extern __shared__ __align__(128) char smem[];
    const uint32_t sbase = smem_u32(smem);
    const int tid = threadIdx.x, lane = tid & 31, wid = tid >> 5;
    const int warp_m = wid >> 2, warp_n = wid & 3;     // 2 x 4 warps, 64x32 warp tile
    const int row0 = blockIdx.x * 128, col0 = blockIdx.y * 128;

    const int kc  = Kp >> 6;            // 64-byte chunks per pass
    const int nch = 3 * kc;

    const int ld_r  = tid >> 2;
    const int ld_sg = (tid & 3) * 16;

    auto loadChunk = [&](int c, int buf) {
        const int p = c / kc;
        const size_t kk = (size_t)(c - p * kc) * 64;
        const int8_t* Ap = (p == 2 ? A2 : A1) + (size_t)row0 * Kp + kk;
        const int8_t* Bp = (p == 1 ? B2 : B1) + (size_t)col0 * Kp + kk;
        const uint32_t sA = sbase + buf * STAGE_BYTES;
        const uint32_t sB = sA + 128 * ROWP;
#pragma unroll
        for (int i = 0; i < 2; i++) {
            const int r = ld_r + i * 64;
            cp_async16(sA + r * ROWP + ld_sg, Ap + (size_t)r * Kp + ld_sg);
            cp_async16(sB + r * ROWP + ld_sg, Bp + (size_t)r * Kp + ld_sg);
        }
        CP_COMMIT();
    };

    int accP[4][4][4], accC[4][4][4];
#pragma unroll
    for (int i = 0; i < 4; i++)
#pragma unroll
        for (int j = 0; j < 4; j++)
#pragma unroll
            for (int q = 0; q < 4; q++) { accP[i][j][q] = 0; accC[i][j][q] = 0; }

    loadChunk(0, 0);
    loadChunk(1, 1);
    loadChunk(2, 2);

    const int a_row = warp_m * 64 + (lane & 15);
    const int a_seg = (lane >> 4);
    const int b_row = warp_n * 32 + (lane & 7) + ((lane >> 4) << 3);
    const int b_seg = (lane >> 3) & 1;

    auto compute = [&](int (&acc)[4][4][4], uint32_t sA, uint32_t sB) {
#pragma unroll
        for (int s = 0; s < 2; s++) {                 // two k32 steps per 64B chunk
            uint32_t a[4][4], b[2][4];
#pragma unroll
            for (int mi = 0; mi < 4; mi++)
                ldm_x4(a[mi][0], a[mi][1], a[mi][2], a[mi][3],
                       sA + (a_row + mi * 16) * ROWP + s * 32 + a_seg * 16);
#pragma unroll
            for (int j = 0; j < 2; j++)
                ldm_x4(b[j][0], b[j][1], b[j][2], b[j][3],
                       sB + (b_row + j * 16) * ROWP + s * 32 + b_seg * 16);
#pragma unroll
            for (int mi = 0; mi < 4; mi++)
#pragma unroll
                for (int ni = 0; ni < 4; ni++)
                    imma16832(acc[mi][ni], a[mi],
                              b[ni >> 1][(ni & 1) * 2], b[ni >> 1][(ni & 1) * 2 + 1]);
        }
    };

    for (int c = 0; c < nch; c++) {
        if (c + 3 <= nch)      { CP_WAIT(2); }
        else if (c + 2 == nch) { CP_WAIT(1); }
        else                   { CP_WAIT(0); }
        __syncthreads();
        if (c + 3 < nch) loadChunk(c + 3, (c + 3) & (NSTAGE - 1));

        const int buf = c & (NSTAGE - 1);
        const uint32_t sA = sbase + buf * STAGE_BYTES;
        const uint32_t sB = sA + 128 * ROWP;
        if (c < kc) compute(accP, sA, sB);
        else        compute(accC, sA, sB);
    }

    // ---------------- epilogue ----------------
    const int g = lane >> 2, tig = lane & 3;
    const float i256 = 1.f / 256.f;
#pragma unroll
    for (int mi = 0; mi < 4; mi++) {
#pragma unroll
        for (int half = 0; half < 2; half++) {
            const int r = row0 + warp_m * 64 + mi * 16 + g + half * 8;
            const float sa = saA[r];
#pragma unroll
            for (int ni = 0; ni < 4; ni++) {
                const int col = col0 + warp_n * 32 + ni * 8 + tig * 2;
                if (col >= Nlog) continue;
                const float2 sb2 = *(const float2*)(sbB + col);
                float v0 = sa * sb2.x * ((float)accP[mi][ni][half * 2 + 0]
                                         + i256 * (float)accC[mi][ni][half * 2 + 0]);
                float v1 = sa * sb2.y * ((float)accP[mi][ni][half * 2 + 1]
                                         + i256 * (float)accC[mi][ni][half * 2 + 1]);
                if (EPI != EPI_NONE) {
                    const float2 bb = *(const float2*)(bias + col);
                    v0 += bb.x; v1 += bb.y;
                }
                if (EPI == EPI_BIAS_SILU) {
                    v0 = v0 / (1.f + __expf(-v0));
                    v1 = v1 / (1.f + __expf(-v1));
                }
                if (EPI == EPI_BIAS_GELU) {
                    v0 = 0.5f * v0 * (1.f + erff(v0 * 0.7071067811865475f));
                    v1 = 0.5f * v1 * (1.f + erff(v1 * 0.7071067811865475f));
                }
                if (EPI == EPI_BIAS_RES) {
                    const float2 rr = *(const float2*)(Rsrc + (size_t)r * Rstride + col);
                    v0 += rr.x; v1 += rr.y;
                }
                if (EPI == EPI_BIAS_MUL) {
                    const float2 rr = *(const float2*)(Rsrc + (size_t)r * Rstride + col);
                    v0 *= rr.x; v1 *= rr.y;
                }
                *(float2*)(C + (size_t)r * Nstride + col) = make_float2(v0, v1);
            }
        }
    }
}

// ---------------- windowed attention with fused RoPE (fp32 out) ----------------
#define ATT_SMEM ((64 * 80 + 64 * 81 + 64 * 80 + 8 * 64) * 4)

__global__ void attn_kernel(const float* __restrict__ qkv, const float* __restrict__ rot,
                            float* __restrict__ out)
{
    extern __shared__ float sm[];
    float* qs = sm;
    float* ks = qs + 64 * 80;
    float* vs = ks + 64 * 81;
    float* pr = vs + 64 * 80;
    const int w = blockIdx.x, hh = blockIdx.y;
    const int tid = threadIdx.x, lane = tid & 31, warp = tid >> 5;
    const size_t base = (size_t)w * WIN * (3 * D_MODEL) + hh * HD;

    for (int idx = tid; idx < WIN * HALF; idx += 256) {
        const int t = idx / HALF, d = idx % HALF;
        float s, c;
        sincosf(rot[(w * WIN + t) * HALF + d], &s, &c);
        const size_t g = base + (size_t)t * (3 * D_MODEL) + d;
        const float qre = qkv[g],           qim = qkv[g + HALF];
        const float kre = qkv[g + D_MODEL], kim = qkv[g + D_MODEL + HALF];
        qs[t * 80 + d]        = qre * c - qim * s;
        qs[t * 80 + d + HALF] = qre * s + qim * c;
        ks[t * 81 + d]        = kre * c - kim * s;
        ks[t * 81 + d + HALF] = kre * s + kim * c;
    }
    for (int idx = tid; idx < WIN * HD; idx += 256) {
        const int t = idx / HD, d = idx % HD;
        vs[t * 80 + d] = qkv[base + (size_t)t * (3 * D_MODEL) + 2 * D_MODEL + d];
    }
    __syncthreads();

    for (int row = warp; row < WIN; row += 8) {
        const float* qr = qs + row * 80;
        const float* k0 = ks + lane * 81;
        const float* k1 = ks + (lane + 32) * 81;
        float s0 = 0.f, s1 = 0.f;
#pragma unroll
        for (int d = 0; d < HD; d++) { const float q = qr[d]; s0 += q * k0[d]; s1 += q * k1[d]; }
        s0 *= ATT_SCALE; s1 *= ATT_SCALE;
        float mx = fmaxf(s0, s1);
#pragma unroll
        for (int o = 16; o; o >>= 1) mx = fmaxf(mx, __shfl_xor_sync(~0u, mx, o));
        const float e0 = __expf(s0 - mx), e1 = __expf(s1 - mx);
        float sum = e0 + e1;
#pragma unroll
        for (int o = 16; o; o >>= 1) sum += __shfl_xor_sync(~0u, sum, o);
        const float inv = 1.f / sum;
        pr[warp * 64 + lane] = e0 * inv;
        pr[warp * 64 + lane + 32] = e1 * inv;
        __syncwarp();
        float o0 = 0.f, o1 = 0.f, o2 = 0.f;
#pragma unroll 4
        for (int j = 0; j < WIN; j++) {
            const float p = pr[warp * 64 + j];
            const float* vr = vs + j * 80;
            o0 += p * vr[lane];
            o1 += p * vr[lane + 32];
            if (lane < 16) o2 += p * vr[lane + 64];
        }
        const size_t ob = (size_t)(w * WIN + row) * D_MODEL + hh * HD;
        out[ob + lane]      = o0;
        out[ob + lane + 32] = o1;
        if (lane < 16) out[ob + lane + 64] = o2;
        __syncwarp();
    }
}

// ---------------- host ----------------
extern "C" void kernel_launch(void* const* d_in, const int* in_sizes, int n_in,
                              void* d_out, int out_size)
{
    const float* x      = (const float*)d_in[0];
    const float* rot    = (const float*)d_in[1];
    const float* patchw = (const float*)d_in[3];
    const float* qkvw   = (const float*)d_in[4];
    const float* qkvb   = (const float*)d_in[5];
    const float* projw  = (const float*)d_in[6];
    const float* projb  = (const float*)d_in[7];
    const float* n1s    = (const float*)d_in[8];
    const float* n2s    = (const float*)d_in[9];
    const float* gw     = (const float*)d_in[10];
    const float* gb     = (const float*)d_in[11];
    const float* uw     = (const float*)d_in[12];
    const float* ub     = (const float*)d_in[13];
    const float* dw     = (const float*)d_in[14];
    const float* db     = (const float*)d_in[15];
    const float* lnq    = (const float*)d_in[16];
    const float* f1w    = (const float*)d_in[17];
    const float* f1b    = (const float*)d_in[18];
    const float* f2w    = (const float*)d_in[19];
    const float* f2b    = (const float*)d_in[20];
    float* out = (float*)d_out;

    float *h, *qkv, *att, *gatef, *upf, *f1f, *wscale;
    float *xq, *nq, *atq, *upq, *f1q;
    int8_t *x1, *x2, *n1, *n2, *at1, *at2, *up1, *up2, *f11, *f12;
    int8_t *patchW1, *patchW2, *qkvW1, *qkvW2, *projW1, *projW2;
    int8_t *gateW1, *gateW2, *upW1, *upW2, *downW1, *downW2;
    int8_t *fc1W1, *fc1W2, *fc2W1, *fc2W2;
#define GA(p, s) cudaGetSymbolAddress((void**)&p, s)
    GA(h, g_h); GA(qkv, g_qkv); GA(att, g_att); GA(gatef, g_gatef);
    GA(upf, g_upf); GA(f1f, g_f1f); GA(wscale, g_wscale);
    GA(xq, g_xq); GA(nq, g_nq); GA(atq, g_atq); GA(upq, g_upq); GA(f1q, g_f1q);
    GA(x1, g_x1); GA(x2, g_x2); GA(n1, g_n1); GA(n2, g_n2);
    GA(at1, g_at1); GA(at2, g_at2); GA(up1, g_up1); GA(up2, g_up2);
    GA(f11, g_f11); GA(f12, g_f12);
    GA(patchW1, g_patchW1); GA(patchW2, g_patchW2);
    GA(qkvW1, g_qkvW1); GA(qkvW2, g_qkvW2);
    GA(projW1, g_projW1); GA(projW2, g_projW2);
    GA(gateW1, g_gateW1); GA(gateW2, g_gateW2);
    GA(upW1, g_upW1); GA(upW2, g_upW2);
    GA(downW1, g_downW1); GA(downW2, g_downW2);
    GA(fc1W1, g_fc1W1); GA(fc1W2, g_fc1W2);
    GA(fc2W1, g_fc2W1); GA(fc2W2, g_fc2W2);
#undef GA

    cudaFuncSetAttribute(attn_kernel, cudaFuncAttributeMaxDynamicSharedMemorySize, ATT_SMEM);
    cudaFuncSetAttribute(gemm_i8<EPI_NONE>,      cudaFuncAttributeMaxDynamicSharedMemorySize, GEMM_SMEM);
    cudaFuncSetAttribute(gemm_i8<EPI_BIAS>,      cudaFuncAttributeMaxDynamicSharedMemorySize, GEMM_SMEM);
    cudaFuncSetAttribute(gemm_i8<EPI_BIAS_RES>,  cudaFuncAttributeMaxDynamicSharedMemorySize, GEMM_SMEM);
    cudaFuncSetAttribute(gemm_i8<EPI_BIAS_SILU>, cudaFuncAttributeMaxDynamicSharedMemorySize, GEMM_SMEM);
    cudaFuncSetAttribute(gemm_i8<EPI_BIAS_MUL>,  cudaFuncAttributeMaxDynamicSharedMemorySize, GEMM_SMEM);
    cudaFuncSetAttribute(gemm_i8<EPI_BIAS_GELU>, cudaFuncAttributeMaxDynamicSharedMemorySize, GEMM_SMEM);

    // ---- build weight tables (colmax + transpose/quantize share ordering) ----
    MTable mt; QTable qt;
    int sbase = 0, blk = 0, tile = 0, si = 0;
    int segbase[NSEG];
    auto add = [&](const float* s, int8_t* d1, int8_t* d2, int K, int N, int Kp, int Np) {
        segbase[si] = sbase;
        mt.seg[si] = { s, K, N, Np, sbase, blk };
        qt.seg[si] = { s, d1, d2, K, N, Kp, sbase, tile, Kp / 32 };
        blk  += (Np + 255) / 256;
        tile += (Kp / 32) * (Np / 32);
        sbase += Np;
        si++;
    };
    add(patchw, patchW1, patchW2, PATCH_IN, 1280, PATCH_KP, 1280);
    for (int l = 0; l < DEPTH; l++) {
        add(qkvw + (size_t)l * 1280 * 3840, qkvW1 + (size_t)l * 3840 * 1280,
            qkvW2 + (size_t)l * 3840 * 1280, 1280, 3840, 1280, 3840);
        add(projw + (size_t)l * 1280 * 1280, projW1 + (size_t)l * 1280 * 1280,
            projW2 + (size_t)l * 1280 * 1280, 1280, 1280, 1280, 1280);
        add(gw + (size_t)l * 1280 * FF_DIM, gateW1 + (size_t)l * FF_PAD * 1280,
            gateW2 + (size_t)l * FF_PAD * 1280, 1280, FF_DIM, 1280, FF_PAD);
        add(uw + (size_t)l * 1280 * FF_DIM, upW1 + (size_t)l * FF_PAD * 1280,
            upW2 + (size_t)l * FF_PAD * 1280, 1280, FF_DIM, 1280, FF_PAD);
        add(dw + (size_t)l * FF_DIM * 1280, downW1 + (size_t)l * 1280 * FF_PAD,
            downW2 + (size_t)l * 1280 * FF_PAD, FF_DIM, 1280, FF_PAD, 1280);
    }
    add(f1w, fc1W1, fc1W2, 5120, 5120, 5120, 5120);
    add(f2w, fc2W1, fc2W2, 5120, 3584, 5120, 3584);

    colmax_all<<<blk, 256>>>(mt);
    conv_all<<<tile, dim3(32, 8)>>>(qt);

    // input quantize
    quant_rows<<<T_TOK, 256>>>(x, x1, x2, xq, PATCH_IN, PATCH_KP, PATCH_IN);

    // segment scale bases in declaration order
    int sb_i = 0;
    const int sb_patch = segbase[sb_i++];
    int sb_qkv[DEPTH], sb_proj[DEPTH], sb_gate[DEPTH], sb_up[DEPTH], sb_down[DEPTH];
    for (int l = 0; l < DEPTH; l++) {
        sb_qkv[l] = segbase[sb_i++]; sb_proj[l] = segbase[sb_i++];
        sb_gate[l] = segbase[sb_i++]; sb_up[l] = segbase[sb_i++]; sb_down[l] = segbase[sb_i++];
    }
    const int sb_fc1 = segbase[sb_i++];
    const int sb_fc2 = segbase[sb_i++];

    // ---- patch embed: h = x @ patch_w ----
    gemm_i8<EPI_NONE><<<dim3(16, 10), 256, GEMM_SMEM>>>(
        x1, x2, patchW1, patchW2, xq, wscale + sb_patch,
        nullptr, nullptr, h, PATCH_KP, 1280, 1280, 0);

    for (int l = 0; l < DEPTH; l++) {
        const size_t lD = (size_t)l * D_MODEL;
        rmsnorm_quant<<<T_TOK, 256>>>(h, n1s + lD, n1, n2, nq);
        gemm_i8<EPI_BIAS><<<dim3(16, 30), 256, GEMM_SMEM>>>(
            n1, n2, qkvW1 + (size_t)l * 3840 * 1280, qkvW2 + (size_t)l * 3840 * 1280,
            nq, wscale + sb_qkv[l], qkvb + (size_t)l * 3840, nullptr, qkv,
            1280, 3840, 3840, 0);
        attn_kernel<<<dim3(NWIN, H_HEADS), 256, ATT_SMEM>>>(qkv, rot, att);
        quant_rows<<<T_TOK, 256>>>(att, at1, at2, atq, D_MODEL, D_MODEL, D_MODEL);
        gemm_i8<EPI_BIAS_RES><<<dim3(16, 10), 256, GEMM_SMEM>>>(
            at1, at2, projW1 + (size_t)l * 1280 * 1280, projW2 + (size_t)l * 1280 * 1280,
            atq, wscale + sb_proj[l], projb + lD, h, h, 1280, 1280, 1280, 1280);
        rmsnorm_quant<<<T_TOK, 256>>>(h, n2s + lD, n1, n2, nq);
        gemm_i8<EPI_BIAS_SILU><<<dim3(16, 27), 256, GEMM_SMEM>>>(
            n1, n2, gateW1 + (size_t)l * FF_PAD * 1280, gateW2 + (size_t)l * FF_PAD * 1280,
            nq, wscale + sb_gate[l], gb + (size_t)l * FF_DIM, nullptr, gatef,
            1280, FF_DIM, FF_DIM, 0);
        gemm_i8<EPI_BIAS_MUL><<<dim3(16, 27), 256, GEMM_SMEM>>>(
            n1, n2, upW1 + (size_t)l * FF_PAD * 1280, upW2 + (size_t)l * FF_PAD * 1280,
            nq, wscale + sb_up[l], ub + (size_t)l * FF_DIM, gatef, upf,
            1280, FF_DIM, FF_DIM, FF_DIM);
        quant_rows<<<T_TOK, 256>>>(upf, up1, up2, upq, FF_DIM, FF_PAD, FF_DIM);
        gemm_i8<EPI_BIAS_RES><<<dim3(16, 10), 256, GEMM_SMEM>>>(
            up1, up2, downW1 + (size_t)l * 1280 * FF_PAD, downW2 + (size_t)l * 1280 * FF_PAD,
            upq, wscale + sb_down[l], db + lD, h, h, FF_PAD, 1280, 1280, 1280);
    }

    // ---- merger ----
    rmsnorm_quant<<<T_TOK, 256>>>(h, lnq, n1, n2, nq);
    // view n planes as [512, 5120]; row scale must be per 5120-row: requantize
    // rmsnorm rows are 1280-wide with per-1280 scales — regroup via fp32 staging:
    // reuse att buffer as fp32 rmsnorm output? simpler: quantize from h via fused norm
    // NOTE: merged rows need a single scale across 4 consecutive 1280-rows.
    // We re-quantize: write fp32 normed output to att, then quant_rows at 5120.
    // (rmsnorm_quant above already wrote planes; overwrite via fp32 path:)
    // -- fp32 rmsnorm into att:
    // reuse quant path: do rmsnorm to fp32 then quant at 5120 granularity.
    {
        // rmsnorm fp32 (via rmsnorm_quant is int8-only) -> small dedicated pass:
        // quantize at merged granularity using fp32 staging in att.
    }
    // fp32 rmsnorm into att
    // (separate kernel below)
    extern __global__ void rmsnorm_f32(const float*, const float*, float*);
    rmsnorm_f32<<<T_TOK, 256>>>(h, lnq, att);
    quant_rows<<<512, 256>>>(att, f11, f12, f1q, 4 * D_MODEL, 4 * D_MODEL, 4 * D_MODEL);
    gemm_i8<EPI_BIAS_GELU><<<dim3(4, 40), 256, GEMM_SMEM>>>(
        f11, f12, fc1W1, fc1W2, f1q, wscale + sb_fc1, f1b, nullptr, f1f,
        5120, 5120, 5120, 0);
    quant_rows<<<512, 256>>>(f1f, f11, f12, f1q, 5120, 5120, 5120);
    gemm_i8<EPI_BIAS><<<dim3(4, 28), 256, GEMM_SMEM>>>(
        f11, f12, fc2W1, fc2W2, f1q, wscale + sb_fc2, f2b, nullptr, out,
        5120, 3584, 3584, 0);
}

// fp32 rmsnorm for the merger path (row scale must span 4 merged rows)
__global__ void rmsnorm_f32(const float* __restrict__ x, const float* __restrict__ s,
                            float* __restrict__ y)
{
    const int row = blockIdx.x;
    const float* xr = x + (size_t)row * D_MODEL;
    float sum = 0.f;
    for (int i = threadIdx.x; i < D_MODEL; i += 256) { const float v = xr[i]; sum += v * v; }
#pragma unroll
    for (int o = 16; o; o >>= 1) sum += __shfl_xor_sync(~0u, sum, o);
    __shared__ float red[8];
    const int warp = threadIdx.x >> 5, lane = threadIdx.x & 31;
    if (lane == 0) red[warp] = sum;
    __syncthreads();
    if (warp == 0) {
        float v = (lane < 8) ? red[lane] : 0.f;
#pragma unroll
        for (int o = 4; o; o >>= 1) v += __shfl_xor_sync(~0u, v, o);
        if (lane == 0) red[0] = v;
    }
    __syncthreads();
    const float rinv = rsqrtf(red[0] * (1.f / D_MODEL) + EPS_RMS);
    for (int i = threadIdx.x; i < D_MODEL; i += 256)
        y[(size_t)row * D_MODEL + i] = xr[i] * s[i] * rinv;
}

// round 7
// speedup vs baseline: 2.4326x; 2.4326x over previous
#include <cuda_runtime.h>
#include <cuda_bf16.h>
#include <math.h>
#include <stdint.h>

// ---------------- problem constants ----------------
#define T_TOK   2048
#define D_MODEL 1280
#define H_HEADS 16
#define HD      80
#define HALF    40
#define FF_DIM  3420
#define FF_PAD  3456
#define FF2     (2 * FF_PAD)          // 6912 fused gate|up
#define DEPTH   4
#define OUT_DIM 3584
#define PATCH_IN 1176
#define PATCH_KP 1216
#define WIN     64
#define NWIN    (T_TOK / WIN)
#define EPS_RMS 1e-6f
#define ATT_SCALE 0.1118033988749895f

typedef __nv_bfloat16 bf16;

// ---------------- helpers ----------------
__device__ __forceinline__ uint32_t smem_u32(const void* p) {
    uint32_t a;
    asm("{ .reg .u64 t; cvta.to.shared.u64 t, %1; cvt.u32.u64 %0, t; }" : "=r"(a) : "l"(p));
    return a;
}
__device__ __forceinline__ void cp_async16(uint32_t s, const void* g) {
    asm volatile("cp.async.cg.shared.global [%0], [%1], 16;" :: "r"(s), "l"(g));
}
#define CP_COMMIT() asm volatile("cp.async.commit_group;" ::: "memory")
#define CP_WAIT(n)  asm volatile("cp.async.wait_group %0;" :: "n"(n) : "memory")

__device__ __forceinline__ void ldm_x4(uint32_t& r0, uint32_t& r1, uint32_t& r2,
                                       uint32_t& r3, uint32_t addr) {
    asm volatile("ldmatrix.sync.aligned.m8n8.x4.shared.b16 {%0,%1,%2,%3}, [%4];"
                 : "=r"(r0), "=r"(r1), "=r"(r2), "=r"(r3) : "r"(addr));
}
__device__ __forceinline__ void mma16816(float* d, const uint32_t* a,
                                         uint32_t b0, uint32_t b1) {
    asm volatile("mma.sync.aligned.m16n8k16.row.col.f32.bf16.bf16.f32 "
                 "{%0,%1,%2,%3}, {%4,%5,%6,%7}, {%8,%9}, {%0,%1,%2,%3};"
                 : "+f"(d[0]), "+f"(d[1]), "+f"(d[2]), "+f"(d[3])
                 : "r"(a[0]), "r"(a[1]), "r"(a[2]), "r"(a[3]), "r"(b0), "r"(b1));
}

// ---------------- scratch ----------------
__device__ float g_h  [T_TOK * D_MODEL];
__device__ float g_qkv[T_TOK * 3 * D_MODEL];
__device__ float g_gu [(size_t)T_TOK * FF2];               // fused gate|up raw
__device__ float g_gub[DEPTH * FF2];                        // concat bias
__device__ bf16  g_xh [T_TOK * PATCH_KP],       g_xl [T_TOK * PATCH_KP];
__device__ bf16  g_nh [T_TOK * D_MODEL],        g_nl [T_TOK * D_MODEL];
__device__ bf16  g_ath[T_TOK * D_MODEL],        g_atl[T_TOK * D_MODEL];
__device__ bf16  g_uph[(size_t)T_TOK * FF_PAD], g_upl[(size_t)T_TOK * FF_PAD];
__device__ bf16  g_f1h[512 * 4 * D_MODEL],      g_f1l[512 * 4 * D_MODEL];
// transposed/split weights [N, Kp]
__device__ bf16 g_patchTh[1280 * PATCH_KP],              g_patchTl[1280 * PATCH_KP];
__device__ bf16 g_qkvTh [DEPTH * 3840 * 1280],           g_qkvTl [DEPTH * 3840 * 1280];
__device__ bf16 g_projTh[DEPTH * 1280 * 1280],           g_projTl[DEPTH * 1280 * 1280];
__device__ bf16 g_guTh  [(size_t)DEPTH * FF2 * 1280],    g_guTl  [(size_t)DEPTH * FF2 * 1280];
__device__ bf16 g_downTh[(size_t)DEPTH * 1280 * FF_PAD], g_downTl[(size_t)DEPTH * 1280 * FF_PAD];
__device__ bf16 g_fc1Th [5120 * 5120],                   g_fc1Tl [5120 * 5120];
__device__ bf16 g_fc2Th [3584 * 5120],                   g_fc2Tl [3584 * 5120];

// ---------------- activation split ----------------
__global__ void conv_act(const float* __restrict__ X, bf16* __restrict__ Xh,
                         bf16* __restrict__ Xl, int M, int K, int Kp) {
    int idx = blockIdx.x * 256 + threadIdx.x;
    if (idx >= M * Kp) return;
    int m = idx / Kp, k = idx - m * Kp;
    float v = (k < K) ? X[(size_t)m * K + k] : 0.f;
    bf16 h = __float2bfloat16(v);
    Xh[idx] = h;
    Xl[idx] = __float2bfloat16(v - __bfloat162float(h));
}

// ---------------- concat bias builder ----------------
__global__ void build_gub(const float* __restrict__ gb, const float* __restrict__ ub) {
    int idx = blockIdx.x * 256 + threadIdx.x;
    if (idx >= DEPTH * FF2) return;
    const int l = idx / FF2, c = idx - l * FF2;
    float v = 0.f;
    if (c < FF_DIM)                          v = gb[l * FF_DIM + c];
    else if (c >= FF_PAD && c < FF_PAD + FF_DIM) v = ub[l * FF_DIM + (c - FF_PAD)];
    g_gub[idx] = v;
}

// ---------------- batched weight transpose+split ----------------
#define NSEG 23
struct Seg { const float* s; bf16* dh; bf16* dl; int K, N, Kp, tile0, tilesX; };
struct ConvTable { Seg seg[NSEG]; };

__global__ void conv_all(ConvTable tb) {
    __shared__ float t[32][33];
    const int tile = blockIdx.x;
    int si = 0;
#pragma unroll
    for (int i = 1; i < NSEG; i++) si += (tb.seg[i].tile0 <= tile);
    const Seg sg = tb.seg[si];
    const int lt = tile - sg.tile0;
    const int kb = (lt % sg.tilesX) * 32;
    const int nb = (lt / sg.tilesX) * 32;
#pragma unroll
    for (int j = 0; j < 32; j += 8) {
        int k = kb + threadIdx.y + j, n = nb + threadIdx.x;
        t[threadIdx.y + j][threadIdx.x] =
            (k < sg.K && n < sg.N) ? sg.s[(size_t)k * sg.N + n] : 0.f;
    }
    __syncthreads();
#pragma unroll
    for (int j = 0; j < 32; j += 8) {
        int n = nb + threadIdx.y + j, k = kb + threadIdx.x;
        if (k < sg.Kp) {
            float v = t[threadIdx.x][threadIdx.y + j];
            bf16 h = __float2bfloat16(v);
            sg.dh[(size_t)n * sg.Kp + k] = h;
            sg.dl[(size_t)n * sg.Kp + k] = __float2bfloat16(v - __bfloat162float(h));
        }
    }
}

// ---------------- HMMA GEMM (split-bf16, 3 passes in one k loop) ----------------
enum { EPI_NONE = 0, EPI_BIAS, EPI_BIAS_RES, EPI_BIAS_GELU };

#define ROWP 80
#define NSTAGE 4

template <int EPI, bool PAIR, int BM>
__global__ __launch_bounds__(256, 2)
void gemm_mma(const bf16* __restrict__ Ah, const bf16* __restrict__ Al,
              const bf16* __restrict__ Bh, const bf16* __restrict__ Bl,
              const float* __restrict__ bias, const float* __restrict__ Rsrc,
              float* __restrict__ C, bf16* __restrict__ Ch, bf16* __restrict__ Cl,
              int Kp, int Nlog, int Nstride, int Rstride)
{
    constexpr int STAGE_BYTES = (BM + 128) * ROWP;
    constexpr int MI = BM / 32;               // mma row-tiles per warp
    extern __shared__ __align__(128) char smem[];
    const uint32_t sbase = smem_u32(smem);
    const int tid = threadIdx.x, lane = tid & 31, wid = tid >> 5;
    const int warp_m = wid >> 2, warp_n = wid & 3;     // 2 x 4 warps
    const int row0 = blockIdx.x * BM, col0 = blockIdx.y * 128;

    const int kc  = Kp >> 5;
    const int nch = 3 * kc;
    const size_t rowB = (size_t)Kp * 2;

    const int ld_r  = tid >> 2;
    const int ld_sg = (tid & 3) * 16;

    auto loadChunk = [&](int c, int buf) {
        const int p = c / kc;
        const size_t kk = (size_t)(c - p * kc) * 64;
        const char* Ap = (const char*)(p == 2 ? Al : Ah) + (size_t)row0 * rowB + kk;
        const char* Bp = (const char*)(p == 1 ? Bl : Bh) + (size_t)col0 * rowB + kk;
        const uint32_t sA = sbase + buf * STAGE_BYTES;
        const uint32_t sB = sA + BM * ROWP;
#pragma unroll
        for (int i = 0; i < BM / 64; i++) {
            const int r = ld_r + i * 64;
            cp_async16(sA + r * ROWP + ld_sg, Ap + (size_t)r * rowB + ld_sg);
        }
#pragma unroll
        for (int i = 0; i < 2; i++) {
            const int r = ld_r + i * 64;
            cp_async16(sB + r * ROWP + ld_sg, Bp + (size_t)r * rowB + ld_sg);
        }
        CP_COMMIT();
    };

    float acc[MI][4][4];
#pragma unroll
    for (int i = 0; i < MI; i++)
#pragma unroll
        for (int j = 0; j < 4; j++)
#pragma unroll
            for (int q = 0; q < 4; q++) acc[i][j][q] = 0.f;

    loadChunk(0, 0);
    loadChunk(1, 1);
    loadChunk(2, 2);

    const int a_row = warp_m * (BM / 2) + (lane & 15);
    const int a_seg = (lane >> 4);
    const int b_row = warp_n * 32 + (lane & 7) + ((lane >> 4) << 3);
    const int b_seg = (lane >> 3) & 1;

    for (int c = 0; c < nch; c++) {
        if (c + 3 <= nch)      { CP_WAIT(2); }
        else if (c + 2 == nch) { CP_WAIT(1); }
        else                   { CP_WAIT(0); }
        __syncthreads();
        if (c + 3 < nch) loadChunk(c + 3, (c + 3) & (NSTAGE - 1));

        const int buf = c & (NSTAGE - 1);
        const uint32_t sA = sbase + buf * STAGE_BYTES;
        const uint32_t sB = sA + BM * ROWP;

#pragma unroll
        for (int s = 0; s < 2; s++) {
            uint32_t a[MI][4], b[2][4];
#pragma unroll
            for (int mi = 0; mi < MI; mi++)
                ldm_x4(a[mi][0], a[mi][1], a[mi][2], a[mi][3],
                       sA + (a_row + mi * 16) * ROWP + (s * 2 + a_seg) * 16);
#pragma unroll
            for (int j = 0; j < 2; j++)
                ldm_x4(b[j][0], b[j][1], b[j][2], b[j][3],
                       sB + (b_row + j * 16) * ROWP + (s * 2 + b_seg) * 16);
#pragma unroll
            for (int mi = 0; mi < MI; mi++)
#pragma unroll
                for (int ni = 0; ni < 4; ni++)
                    mma16816(acc[mi][ni], a[mi],
                             b[ni >> 1][(ni & 1) * 2], b[ni >> 1][(ni & 1) * 2 + 1]);
        }
    }

    // ---------------- epilogue ----------------
    const int g = lane >> 2, tig = lane & 3;
#pragma unroll
    for (int mi = 0; mi < MI; mi++) {
#pragma unroll
        for (int half = 0; half < 2; half++) {
            const int r = row0 + warp_m * (BM / 2) + mi * 16 + g + half * 8;
#pragma unroll
            for (int ni = 0; ni < 4; ni++) {
                const int col = col0 + warp_n * 32 + ni * 8 + tig * 2;
                float v0 = acc[mi][ni][half * 2 + 0];
                float v1 = acc[mi][ni][half * 2 + 1];
                const bool ok = (col < Nlog);
                if (EPI != EPI_NONE && ok) {
                    const float2 bb = *(const float2*)(bias + col);
                    v0 += bb.x; v1 += bb.y;
                }
                if (EPI == EPI_BIAS_GELU) {
                    v0 = 0.5f * v0 * (1.f + erff(v0 * 0.7071067811865475f));
                    v1 = 0.5f * v1 * (1.f + erff(v1 * 0.7071067811865475f));
                }
                if (EPI == EPI_BIAS_RES && ok) {
                    const float2 rr = *(const float2*)(Rsrc + (size_t)r * Rstride + col);
                    v0 += rr.x; v1 += rr.y;
                }
                if (PAIR) {
                    if (!ok) { v0 = 0.f; v1 = 0.f; }
                    const bf16 h0 = __float2bfloat16(v0);
                    const bf16 h1 = __float2bfloat16(v1);
                    const bf16 l0 = __float2bfloat16(v0 - __bfloat162float(h0));
                    const bf16 l1 = __float2bfloat16(v1 - __bfloat162float(h1));
                    *(__nv_bfloat162*)(Ch + (size_t)r * Nstride + col) = __nv_bfloat162(h0, h1);
                    *(__nv_bfloat162*)(Cl + (size_t)r * Nstride + col) = __nv_bfloat162(l0, l1);
                } else if (ok) {
                    *(float2*)(C + (size_t)r * Nstride + col) = make_float2(v0, v1);
                }
            }
        }
    }
}

// ---------------- silu(gate)*up + bf16 hi/lo split ----------------
__global__ void silu_mul_quant(const float* __restrict__ GU,
                               bf16* __restrict__ Uh, bf16* __restrict__ Ul)
{
    const int row = blockIdx.x;
    const float* gr = GU + (size_t)row * FF2;
    bf16* uh = Uh + (size_t)row * FF_PAD;
    bf16* ul = Ul + (size_t)row * FF_PAD;
    for (int i = threadIdx.x; i < FF_PAD; i += 256) {
        float v = 0.f;
        if (i < FF_DIM) {
            const float gv = gr[i];
            v = (gv / (1.f + __expf(-gv))) * gr[FF_PAD + i];
        }
        const bf16 h = __float2bfloat16(v);
        uh[i] = h;
        ul[i] = __float2bfloat16(v - __bfloat162float(h));
    }
}

// ---------------- rmsnorm -> bf16 hi/lo ----------------
__global__ void rmsnorm_pair(const float* __restrict__ x, const float* __restrict__ s,
                             bf16* __restrict__ yh, bf16* __restrict__ yl)
{
    const int row = blockIdx.x;
    const float* xr = x + (size_t)row * D_MODEL;
    float sum = 0.f;
    for (int i = threadIdx.x; i < D_MODEL; i += 256) { float v = xr[i]; sum += v * v; }
#pragma unroll
    for (int o = 16; o; o >>= 1) sum += __shfl_xor_sync(~0u, sum, o);
    __shared__ float red[8];
    const int warp = threadIdx.x >> 5, lane = threadIdx.x & 31;
    if (lane == 0) red[warp] = sum;
    __syncthreads();
    if (warp == 0) {
        float v = (lane < 8) ? red[lane] : 0.f;
#pragma unroll
        for (int o = 4; o; o >>= 1) v += __shfl_xor_sync(~0u, v, o);
        if (lane == 0) red[0] = v;
    }
    __syncthreads();
    const float rinv = rsqrtf(red[0] * (1.f / D_MODEL) + EPS_RMS);
    for (int i = threadIdx.x; i < D_MODEL; i += 256) {
        float v = xr[i] * s[i] * rinv;
        bf16 h = __float2bfloat16(v);
        yh[(size_t)row * D_MODEL + i] = h;
        yl[(size_t)row * D_MODEL + i] = __float2bfloat16(v - __bfloat162float(h));
    }
}

// ---------------- windowed attention with fused RoPE -> bf16 hi/lo ----------------
#define ATT_SMEM ((64 * 80 + 64 * 81 + 64 * 80 + 8 * 64) * 4)

__global__ void attn_kernel(const float* __restrict__ qkv, const float* __restrict__ rot,
                            bf16* __restrict__ oh, bf16* __restrict__ ol)
{
    extern __shared__ float sm[];
    float* qs = sm;
    float* ks = qs + 64 * 80;
    float* vs = ks + 64 * 81;
    float* pr = vs + 64 * 80;
    const int w = blockIdx.x, hh = blockIdx.y;
    const int tid = threadIdx.x, lane = tid & 31, warp = tid >> 5;
    const size_t base = (size_t)w * WIN * (3 * D_MODEL) + hh * HD;

    for (int idx = tid; idx < WIN * HALF; idx += 256) {
        const int t = idx / HALF, d = idx % HALF;
        float s, c;
        sincosf(rot[(w * WIN + t) * HALF + d], &s, &c);
        const size_t g = base + (size_t)t * (3 * D_MODEL) + d;
        const float qre = qkv[g],           qim = qkv[g + HALF];
        const float kre = qkv[g + D_MODEL], kim = qkv[g + D_MODEL + HALF];
        qs[t * 80 + d]        = qre * c - qim * s;
        qs[t * 80 + d + HALF] = qre * s + qim * c;
        ks[t * 81 + d]        = kre * c - kim * s;
        ks[t * 81 + d + HALF] = kre * s + kim * c;
    }
    for (int idx = tid; idx < WIN * HD; idx += 256) {
        const int t = idx / HD, d = idx % HD;
        vs[t * 80 + d] = qkv[base + (size_t)t * (3 * D_MODEL) + 2 * D_MODEL + d];
    }
    __syncthreads();

    for (int row = warp; row < WIN; row += 8) {
        const float* qr = qs + row * 80;
        const float* k0 = ks + lane * 81;
        const float* k1 = ks + (lane + 32) * 81;
        float s0 = 0.f, s1 = 0.f;
#pragma unroll
        for (int d = 0; d < HD; d++) { const float q = qr[d]; s0 += q * k0[d]; s1 += q * k1[d]; }
        s0 *= ATT_SCALE; s1 *= ATT_SCALE;
        float mx = fmaxf(s0, s1);
#pragma unroll
        for (int o = 16; o; o >>= 1) mx = fmaxf(mx, __shfl_xor_sync(~0u, mx, o));
        const float e0 = __expf(s0 - mx), e1 = __expf(s1 - mx);
        float sum = e0 + e1;
#pragma unroll
        for (int o = 16; o; o >>= 1) sum += __shfl_xor_sync(~0u, sum, o);
        const float inv = 1.f / sum;
        pr[warp * 64 + lane] = e0 * inv;
        pr[warp * 64 + lane + 32] = e1 * inv;
        __syncwarp();
        float o0 = 0.f, o1 = 0.f, o2 = 0.f;
#pragma unroll 4
        for (int j = 0; j < WIN; j++) {
            const float p = pr[warp * 64 + j];
            const float* vr = vs + j * 80;
            o0 += p * vr[lane];
            o1 += p * vr[lane + 32];
            if (lane < 16) o2 += p * vr[lane + 64];
        }
        const size_t ob = (size_t)(w * WIN + row) * D_MODEL + hh * HD;
        bf16 h;
        h = __float2bfloat16(o0); oh[ob + lane] = h;
        ol[ob + lane] = __float2bfloat16(o0 - __bfloat162float(h));
        h = __float2bfloat16(o1); oh[ob + lane + 32] = h;
        ol[ob + lane + 32] = __float2bfloat16(o1 - __bfloat162float(h));
        if (lane < 16) {
            h = __float2bfloat16(o2); oh[ob + lane + 64] = h;
            ol[ob + lane + 64] = __float2bfloat16(o2 - __bfloat162float(h));
        }
        __syncwarp();
    }
}

// ---------------- host ----------------
#define SMEM_OF(BM) ((NSTAGE) * ((BM) + 128) * ROWP)

extern "C" void kernel_launch(void* const* d_in, const int* in_sizes, int n_in,
                              void* d_out, int out_size)
{
    const float* x      = (const float*)d_in[0];
    const float* rot    = (const float*)d_in[1];
    const float* patchw = (const float*)d_in[3];
    const float* qkvw   = (const float*)d_in[4];
    const float* qkvb   = (const float*)d_in[5];
    const float* projw  = (const float*)d_in[6];
    const float* projb  = (const float*)d_in[7];
    const float* n1s    = (const float*)d_in[8];
    const float* n2s    = (const float*)d_in[9];
    const float* gw     = (const float*)d_in[10];
    const float* gb     = (const float*)d_in[11];
    const float* uw     = (const float*)d_in[12];
    const float* ub     = (const float*)d_in[13];
    const float* dw     = (const float*)d_in[14];
    const float* db     = (const float*)d_in[15];
    const float* lnq    = (const float*)d_in[16];
    const float* f1w    = (const float*)d_in[17];
    const float* f1b    = (const float*)d_in[18];
    const float* f2w    = (const float*)d_in[19];
    const float* f2b    = (const float*)d_in[20];
    float* out = (float*)d_out;

    float *h, *qkv, *gu, *gub;
    bf16 *xh, *xl, *nh, *nl, *ath, *atl, *uph, *upl, *f1h, *f1l;
    bf16 *patchTh, *patchTl, *qkvTh, *qkvTl, *projTh, *projTl;
    bf16 *guTh, *guTl, *downTh, *downTl, *fc1Th, *fc1Tl, *fc2Th, *fc2Tl;
#define GA(p, s) cudaGetSymbolAddress((void**)&p, s)
    GA(h, g_h); GA(qkv, g_qkv); GA(gu, g_gu); GA(gub, g_gub);
    GA(xh, g_xh); GA(xl, g_xl); GA(nh, g_nh); GA(nl, g_nl);
    GA(ath, g_ath); GA(atl, g_atl); GA(uph, g_uph); GA(upl, g_upl);
    GA(f1h, g_f1h); GA(f1l, g_f1l);
    GA(patchTh, g_patchTh); GA(patchTl, g_patchTl);
    GA(qkvTh, g_qkvTh); GA(qkvTl, g_qkvTl);
    GA(projTh, g_projTh); GA(projTl, g_projTl);
    GA(guTh, g_guTh); GA(guTl, g_guTl);
    GA(downTh, g_downTh); GA(downTl, g_downTl);
    GA(fc1Th, g_fc1Th); GA(fc1Tl, g_fc1Tl);
    GA(fc2Th, g_fc2Th); GA(fc2Tl, g_fc2Tl);
#undef GA

    cudaFuncSetAttribute(attn_kernel, cudaFuncAttributeMaxDynamicSharedMemorySize, ATT_SMEM);
    cudaFuncSetAttribute(gemm_mma<EPI_NONE, false, 64>,     cudaFuncAttributeMaxDynamicSharedMemorySize, SMEM_OF(64));
    cudaFuncSetAttribute(gemm_mma<EPI_BIAS, false, 128>,    cudaFuncAttributeMaxDynamicSharedMemorySize, SMEM_OF(128));
    cudaFuncSetAttribute(gemm_mma<EPI_BIAS_RES, false, 64>, cudaFuncAttributeMaxDynamicSharedMemorySize, SMEM_OF(64));
    cudaFuncSetAttribute(gemm_mma<EPI_BIAS_GELU, true, 64>, cudaFuncAttributeMaxDynamicSharedMemorySize, SMEM_OF(64));

    // ---- setup: splits + weight conversion ----
    conv_act<<<(T_TOK * PATCH_KP + 255) / 256, 256>>>(x, xh, xl, T_TOK, PATCH_IN, PATCH_KP);
    build_gub<<<(DEPTH * FF2 + 255) / 256, 256>>>(gb, ub);
    {
        ConvTable tb;
        int tc = 0, si = 0;
        auto add = [&](const float* s, bf16* dh, bf16* dl, int K, int N, int Kp, int Np) {
            const int tx = (Kp + 31) / 32, ty = (Np + 31) / 32;
            tb.seg[si] = { s, dh, dl, K, N, Kp, tc, tx };
            tc += tx * ty; si++;
        };
        add(patchw, patchTh, patchTl, PATCH_IN, 1280, PATCH_KP, 1280);
        for (int l = 0; l < DEPTH; l++) {
            add(qkvw + (size_t)l * 1280 * 3840, qkvTh + (size_t)l * 3840 * 1280,
                qkvTl + (size_t)l * 3840 * 1280, 1280, 3840, 1280, 3840);
            add(projw + (size_t)l * 1280 * 1280, projTh + (size_t)l * 1280 * 1280,
                projTl + (size_t)l * 1280 * 1280, 1280, 1280, 1280, 1280);
            // gate -> first FF_PAD rows of fused [FF2, 1280] block
            add(gw + (size_t)l * 1280 * FF_DIM, guTh + (size_t)l * FF2 * 1280,
                guTl + (size_t)l * FF2 * 1280, 1280, FF_DIM, 1280, FF_PAD);
            // up -> second FF_PAD rows
            add(uw + (size_t)l * 1280 * FF_DIM,
                guTh + (size_t)l * FF2 * 1280 + (size_t)FF_PAD * 1280,
                guTl + (size_t)l * FF2 * 1280 + (size_t)FF_PAD * 1280,
                1280, FF_DIM, 1280, FF_PAD);
            add(dw + (size_t)l * FF_DIM * 1280, downTh + (size_t)l * 1280 * FF_PAD,
                downTl + (size_t)l * 1280 * FF_PAD, FF_DIM, 1280, FF_PAD, 1280);
        }
        add(f1w, fc1Th, fc1Tl, 5120, 5120, 5120, 5120);
        add(f2w, fc2Th, fc2Tl, 5120, 3584, 5120, 3584);
        conv_all<<<tc, dim3(32, 8)>>>(tb);
    }

    // ---- patch embed (BM=64) ----
    gemm_mma<EPI_NONE, false, 64><<<dim3(32, 10), 256, SMEM_OF(64)>>>(
        xh, xl, patchTh, patchTl, nullptr, nullptr, h, nullptr, nullptr,
        PATCH_KP, 1280, 1280, 0);

    for (int l = 0; l < DEPTH; l++) {
        const size_t lD = (size_t)l * D_MODEL;
        rmsnorm_pair<<<T_TOK, 256>>>(h, n1s + lD, nh, nl);
        gemm_mma<EPI_BIAS, false, 128><<<dim3(16, 30), 256, SMEM_OF(128)>>>(
            nh, nl, qkvTh + (size_t)l * 3840 * 1280, qkvTl + (size_t)l * 3840 * 1280,
            qkvb + (size_t)l * 3840, nullptr, qkv, nullptr, nullptr, 1280, 3840, 3840, 0);
        attn_kernel<<<dim3(NWIN, H_HEADS), 256, ATT_SMEM>>>(qkv, rot, ath, atl);
        gemm_mma<EPI_BIAS_RES, false, 64><<<dim3(32, 10), 256, SMEM_OF(64)>>>(
            ath, atl, projTh + (size_t)l * 1280 * 1280, projTl + (size_t)l * 1280 * 1280,
            projb + lD, h, h, nullptr, nullptr, 1280, 1280, 1280, 1280);
        rmsnorm_pair<<<T_TOK, 256>>>(h, n2s + lD, nh, nl);
        // fused gate|up GEMM (N = 6912)
        gemm_mma<EPI_BIAS, false, 128><<<dim3(16, FF2 / 128), 256, SMEM_OF(128)>>>(
            nh, nl, guTh + (size_t)l * FF2 * 1280, guTl + (size_t)l * FF2 * 1280,
            gub + (size_t)l * FF2, nullptr, gu, nullptr, nullptr, 1280, FF2, FF2, 0);
        silu_mul_quant<<<T_TOK, 256>>>(gu, uph, upl);
        gemm_mma<EPI_BIAS_RES, false, 64><<<dim3(32, 10), 256, SMEM_OF(64)>>>(
            uph, upl, downTh + (size_t)l * 1280 * FF_PAD, downTl + (size_t)l * 1280 * FF_PAD,
            db + lD, h, h, nullptr, nullptr, FF_PAD, 1280, 1280, 1280);
    }

    // ---- merger ----
    rmsnorm_pair<<<T_TOK, 256>>>(h, lnq, nh, nl);           // viewed as [512, 5120]
    gemm_mma<EPI_BIAS_GELU, true, 64><<<dim3(8, 40), 256, SMEM_OF(64)>>>(
        nh, nl, fc1Th, fc1Tl, f1b, nullptr, nullptr, f1h, f1l, 5120, 5120, 5120, 0);
    gemm_mma<EPI_BIAS, false, 128><<<dim3(4, 28), 256, SMEM_OF(128)>>>(
        f1h, f1l, fc2Th, fc2Tl, f2b, nullptr, out, nullptr, nullptr, 5120, 3584, 3584, 0);
}

// round 8
// speedup vs baseline: 2.8886x; 1.1875x over previous
#include <cuda_runtime.h>
#include <cuda_bf16.h>
#include <math.h>
#include <stdint.h>

// ---------------- problem constants ----------------
#define T_TOK   2048
#define D_MODEL 1280
#define H_HEADS 16
#define HD      80
#define HALF    40
#define FF_DIM  3420
#define FF_PAD  3456
#define FF2     (2 * FF_PAD)          // 6912 fused gate|up
#define DEPTH   4
#define OUT_DIM 3584
#define PATCH_IN 1176
#define PATCH_KP 1216
#define WIN     64
#define NWIN    (T_TOK / WIN)
#define EPS_RMS 1e-6f
#define ATT_SCALE 0.1118033988749895f

typedef __nv_bfloat16 bf16;

// ---------------- helpers ----------------
__device__ __forceinline__ uint32_t smem_u32(const void* p) {
    uint32_t a;
    asm("{ .reg .u64 t; cvta.to.shared.u64 t, %1; cvt.u32.u64 %0, t; }" : "=r"(a) : "l"(p));
    return a;
}
__device__ __forceinline__ void cp_async16(uint32_t s, const void* g) {
    asm volatile("cp.async.cg.shared.global [%0], [%1], 16;" :: "r"(s), "l"(g));
}
#define CP_COMMIT() asm volatile("cp.async.commit_group;" ::: "memory")
#define CP_WAIT(n)  asm volatile("cp.async.wait_group %0;" :: "n"(n) : "memory")

__device__ __forceinline__ void ldm_x4(uint32_t& r0, uint32_t& r1, uint32_t& r2,
                                       uint32_t& r3, uint32_t addr) {
    asm volatile("ldmatrix.sync.aligned.m8n8.x4.shared.b16 {%0,%1,%2,%3}, [%4];"
                 : "=r"(r0), "=r"(r1), "=r"(r2), "=r"(r3) : "r"(addr));
}
__device__ __forceinline__ void mma16816(float* d, const uint32_t* a,
                                         uint32_t b0, uint32_t b1) {
    asm volatile("mma.sync.aligned.m16n8k16.row.col.f32.bf16.bf16.f32 "
                 "{%0,%1,%2,%3}, {%4,%5,%6,%7}, {%8,%9}, {%0,%1,%2,%3};"
                 : "+f"(d[0]), "+f"(d[1]), "+f"(d[2]), "+f"(d[3])
                 : "r"(a[0]), "r"(a[1]), "r"(a[2]), "r"(a[3]), "r"(b0), "r"(b1));
}

// ---------------- scratch ----------------
__device__ float g_h  [T_TOK * D_MODEL];
__device__ float g_qkv[T_TOK * 3 * D_MODEL];
__device__ float g_gu [(size_t)T_TOK * FF2];
__device__ float g_gub[DEPTH * FF2];
__device__ float g_part[(size_t)8 * 512 * 5120];   // split-K partials (84 MB, max use fc1)
__device__ bf16  g_xh [T_TOK * PATCH_KP],       g_xl [T_TOK * PATCH_KP];
__device__ bf16  g_nh [T_TOK * D_MODEL],        g_nl [T_TOK * D_MODEL];
__device__ bf16  g_ath[T_TOK * D_MODEL],        g_atl[T_TOK * D_MODEL];
__device__ bf16  g_uph[(size_t)T_TOK * FF_PAD], g_upl[(size_t)T_TOK * FF_PAD];
__device__ bf16  g_f1h[512 * 4 * D_MODEL],      g_f1l[512 * 4 * D_MODEL];
// transposed/split weights [N, Kp]
__device__ bf16 g_patchTh[1280 * PATCH_KP],              g_patchTl[1280 * PATCH_KP];
__device__ bf16 g_qkvTh [DEPTH * 3840 * 1280],           g_qkvTl [DEPTH * 3840 * 1280];
__device__ bf16 g_projTh[DEPTH * 1280 * 1280],           g_projTl[DEPTH * 1280 * 1280];
__device__ bf16 g_guTh  [(size_t)DEPTH * FF2 * 1280],    g_guTl  [(size_t)DEPTH * FF2 * 1280];
__device__ bf16 g_downTh[(size_t)DEPTH * 1280 * FF_PAD], g_downTl[(size_t)DEPTH * 1280 * FF_PAD];
__device__ bf16 g_fc1Th [5120 * 5120],                   g_fc1Tl [5120 * 5120];
__device__ bf16 g_fc2Th [3584 * 5120],                   g_fc2Tl [3584 * 5120];

// ---------------- activation split ----------------
__global__ void conv_act(const float* __restrict__ X, bf16* __restrict__ Xh,
                         bf16* __restrict__ Xl, int M, int K, int Kp) {
    int idx = blockIdx.x * 256 + threadIdx.x;
    if (idx >= M * Kp) return;
    int m = idx / Kp, k = idx - m * Kp;
    float v = (k < K) ? X[(size_t)m * K + k] : 0.f;
    bf16 h = __float2bfloat16(v);
    Xh[idx] = h;
    Xl[idx] = __float2bfloat16(v - __bfloat162float(h));
}

// ---------------- concat bias builder ----------------
__global__ void build_gub(const float* __restrict__ gb, const float* __restrict__ ub) {
    int idx = blockIdx.x * 256 + threadIdx.x;
    if (idx >= DEPTH * FF2) return;
    const int l = idx / FF2, c = idx - l * FF2;
    float v = 0.f;
    if (c < FF_DIM)                              v = gb[l * FF_DIM + c];
    else if (c >= FF_PAD && c < FF_PAD + FF_DIM) v = ub[l * FF_DIM + (c - FF_PAD)];
    g_gub[idx] = v;
}

// ---------------- batched weight transpose+split ----------------
#define NSEG 23
struct Seg { const float* s; bf16* dh; bf16* dl; int K, N, Kp, tile0, tilesX; };
struct ConvTable { Seg seg[NSEG]; };

__global__ void conv_all(ConvTable tb) {
    __shared__ float t[32][33];
    const int tile = blockIdx.x;
    int si = 0;
#pragma unroll
    for (int i = 1; i < NSEG; i++) si += (tb.seg[i].tile0 <= tile);
    const Seg sg = tb.seg[si];
    const int lt = tile - sg.tile0;
    const int kb = (lt % sg.tilesX) * 32;
    const int nb = (lt / sg.tilesX) * 32;
#pragma unroll
    for (int j = 0; j < 32; j += 8) {
        int k = kb + threadIdx.y + j, n = nb + threadIdx.x;
        t[threadIdx.y + j][threadIdx.x] =
            (k < sg.K && n < sg.N) ? sg.s[(size_t)k * sg.N + n] : 0.f;
    }
    __syncthreads();
#pragma unroll
    for (int j = 0; j < 32; j += 8) {
        int n = nb + threadIdx.y + j, k = kb + threadIdx.x;
        if (k < sg.Kp) {
            float v = t[threadIdx.x][threadIdx.y + j];
            bf16 h = __float2bfloat16(v);
            sg.dh[(size_t)n * sg.Kp + k] = h;
            sg.dl[(size_t)n * sg.Kp + k] = __float2bfloat16(v - __bfloat162float(h));
        }
    }
}

// ---------------- shared GEMM machinery (BM=128, BN=128, 4-stage) ----------------
#define ROWP 80
#define STAGE_BYTES (2 * 128 * ROWP)
#define NSTAGE 4
#define GEMM_SMEM (NSTAGE * STAGE_BYTES)

// ---- full GEMM with fused bias (for gu and fc2; N multiple of 128) ----
__global__ __launch_bounds__(256, 2)
void gemm_bias(const bf16* __restrict__ Ah, const bf16* __restrict__ Al,
               const bf16* __restrict__ Bh, const bf16* __restrict__ Bl,
               const float* __restrict__ bias, float* __restrict__ C,
               int Kp, int N)
{
    extern __shared__ __align__(128) char smem[];
    const uint32_t sbase = smem_u32(smem);
    const int tid = threadIdx.x, lane = tid & 31, wid = tid >> 5;
    const int warp_m = wid >> 2, warp_n = wid & 3;
    const int row0 = blockIdx.x * 128, col0 = blockIdx.y * 128;

    const int kc  = Kp >> 5;
    const int nch = 3 * kc;
    const size_t rowB = (size_t)Kp * 2;
    const int ld_r  = tid >> 2;
    const int ld_sg = (tid & 3) * 16;

    auto loadChunk = [&](int c, int buf) {
        const int p = c / kc;
        const size_t kk = (size_t)(c - p * kc) * 64;
        const char* Ap = (const char*)(p == 2 ? Al : Ah) + (size_t)row0 * rowB + kk;
        const char* Bp = (const char*)(p == 1 ? Bl : Bh) + (size_t)col0 * rowB + kk;
        const uint32_t sA = sbase + buf * STAGE_BYTES;
        const uint32_t sB = sA + 128 * ROWP;
#pragma unroll
        for (int i = 0; i < 2; i++) {
            const int r = ld_r + i * 64;
            cp_async16(sA + r * ROWP + ld_sg, Ap + (size_t)r * rowB + ld_sg);
            cp_async16(sB + r * ROWP + ld_sg, Bp + (size_t)r * rowB + ld_sg);
        }
        CP_COMMIT();
    };

    float acc[4][4][4];
#pragma unroll
    for (int i = 0; i < 4; i++)
#pragma unroll
        for (int j = 0; j < 4; j++)
#pragma unroll
            for (int q = 0; q < 4; q++) acc[i][j][q] = 0.f;

    loadChunk(0, 0); loadChunk(1, 1); loadChunk(2, 2);

    const int a_row = warp_m * 64 + (lane & 15);
    const int a_seg = (lane >> 4);
    const int b_row = warp_n * 32 + (lane & 7) + ((lane >> 4) << 3);
    const int b_seg = (lane >> 3) & 1;

    for (int c = 0; c < nch; c++) {
        if (c + 3 <= nch)      { CP_WAIT(2); }
        else if (c + 2 == nch) { CP_WAIT(1); }
        else                   { CP_WAIT(0); }
        __syncthreads();
        if (c + 3 < nch) loadChunk(c + 3, (c + 3) & (NSTAGE - 1));

        const int buf = c & (NSTAGE - 1);
        const uint32_t sA = sbase + buf * STAGE_BYTES;
        const uint32_t sB = sA + 128 * ROWP;
#pragma unroll
        for (int s = 0; s < 2; s++) {
            uint32_t a[4][4], b[2][4];
#pragma unroll
            for (int mi = 0; mi < 4; mi++)
                ldm_x4(a[mi][0], a[mi][1], a[mi][2], a[mi][3],
                       sA + (a_row + mi * 16) * ROWP + (s * 2 + a_seg) * 16);
#pragma unroll
            for (int j = 0; j < 2; j++)
                ldm_x4(b[j][0], b[j][1], b[j][2], b[j][3],
                       sB + (b_row + j * 16) * ROWP + (s * 2 + b_seg) * 16);
#pragma unroll
            for (int mi = 0; mi < 4; mi++)
#pragma unroll
                for (int ni = 0; ni < 4; ni++)
                    mma16816(acc[mi][ni], a[mi],
                             b[ni >> 1][(ni & 1) * 2], b[ni >> 1][(ni & 1) * 2 + 1]);
        }
    }

    const int g = lane >> 2, tig = lane & 3;
#pragma unroll
    for (int mi = 0; mi < 4; mi++)
#pragma unroll
        for (int half = 0; half < 2; half++) {
            const int r = row0 + warp_m * 64 + mi * 16 + g + half * 8;
#pragma unroll
            for (int ni = 0; ni < 4; ni++) {
                const int col = col0 + warp_n * 32 + ni * 8 + tig * 2;
                const float2 bb = *(const float2*)(bias + col);
                const float v0 = acc[mi][ni][half * 2 + 0] + bb.x;
                const float v1 = acc[mi][ni][half * 2 + 1] + bb.y;
                *(float2*)(C + (size_t)r * N + col) = make_float2(v0, v1);
            }
        }
}

// ---- split-K GEMM: writes raw partials (grid.z = split index) ----
__global__ __launch_bounds__(256, 2)
void gemm_part(const bf16* __restrict__ Ah, const bf16* __restrict__ Al,
               const bf16* __restrict__ Bh, const bf16* __restrict__ Bl,
               float* __restrict__ part, size_t pstride,
               int Kp, int N)
{
    extern __shared__ __align__(128) char smem[];
    const uint32_t sbase = smem_u32(smem);
    const int tid = threadIdx.x, lane = tid & 31, wid = tid >> 5;
    const int warp_m = wid >> 2, warp_n = wid & 3;
    const int row0 = blockIdx.x * 128, col0 = blockIdx.y * 128;
    const int S = gridDim.z, sidx = blockIdx.z;

    const int kc  = Kp >> 5;
    const int nch = 3 * kc;
    const int c0 = (sidx * nch) / S;
    const int c1 = ((sidx + 1) * nch) / S;
    const size_t rowB = (size_t)Kp * 2;
    const int ld_r  = tid >> 2;
    const int ld_sg = (tid & 3) * 16;

    auto loadChunk = [&](int c, int buf) {
        const int p = c / kc;
        const size_t kk = (size_t)(c - p * kc) * 64;
        const char* Ap = (const char*)(p == 2 ? Al : Ah) + (size_t)row0 * rowB + kk;
        const char* Bp = (const char*)(p == 1 ? Bl : Bh) + (size_t)col0 * rowB + kk;
        const uint32_t sA = sbase + buf * STAGE_BYTES;
        const uint32_t sB = sA + 128 * ROWP;
#pragma unroll
        for (int i = 0; i < 2; i++) {
            const int r = ld_r + i * 64;
            cp_async16(sA + r * ROWP + ld_sg, Ap + (size_t)r * rowB + ld_sg);
            cp_async16(sB + r * ROWP + ld_sg, Bp + (size_t)r * rowB + ld_sg);
        }
        CP_COMMIT();
    };

    float acc[4][4][4];
#pragma unroll
    for (int i = 0; i < 4; i++)
#pragma unroll
        for (int j = 0; j < 4; j++)
#pragma unroll
            for (int q = 0; q < 4; q++) acc[i][j][q] = 0.f;

    loadChunk(c0, 0); loadChunk(c0 + 1, 1); loadChunk(c0 + 2, 2);

    const int a_row = warp_m * 64 + (lane & 15);
    const int a_seg = (lane >> 4);
    const int b_row = warp_n * 32 + (lane & 7) + ((lane >> 4) << 3);
    const int b_seg = (lane >> 3) & 1;

    for (int c = c0; c < c1; c++) {
        if (c + 3 <= c1)      { CP_WAIT(2); }
        else if (c + 2 == c1) { CP_WAIT(1); }
        else                  { CP_WAIT(0); }
        __syncthreads();
        if (c + 3 < c1) loadChunk(c + 3, (c - c0 + 3) & (NSTAGE - 1));

        const int buf = (c - c0) & (NSTAGE - 1);
        const uint32_t sA = sbase + buf * STAGE_BYTES;
        const uint32_t sB = sA + 128 * ROWP;
#pragma unroll
        for (int s = 0; s < 2; s++) {
            uint32_t a[4][4], b[2][4];
#pragma unroll
            for (int mi = 0; mi < 4; mi++)
                ldm_x4(a[mi][0], a[mi][1], a[mi][2], a[mi][3],
                       sA + (a_row + mi * 16) * ROWP + (s * 2 + a_seg) * 16);
#pragma unroll
            for (int j = 0; j < 2; j++)
                ldm_x4(b[j][0], b[j][1], b[j][2], b[j][3],
                       sB + (b_row + j * 16) * ROWP + (s * 2 + b_seg) * 16);
#pragma unroll
            for (int mi = 0; mi < 4; mi++)
#pragma unroll
                for (int ni = 0; ni < 4; ni++)
                    mma16816(acc[mi][ni], a[mi],
                             b[ni >> 1][(ni & 1) * 2], b[ni >> 1][(ni & 1) * 2 + 1]);
        }
    }

    float* P = part + (size_t)sidx * pstride;
    const int g = lane >> 2, tig = lane & 3;
#pragma unroll
    for (int mi = 0; mi < 4; mi++)
#pragma unroll
        for (int half = 0; half < 2; half++) {
            const int r = row0 + warp_m * 64 + mi * 16 + g + half * 8;
#pragma unroll
            for (int ni = 0; ni < 4; ni++) {
                const int col = col0 + warp_n * 32 + ni * 8 + tig * 2;
                *(float2*)(P + (size_t)r * N + col) =
                    make_float2(acc[mi][ni][half * 2 + 0], acc[mi][ni][half * 2 + 1]);
            }
        }
}

// ---------------- split-K reduce kernels (deterministic fixed-order sums) ----------------
__global__ void reduce_none(const float* __restrict__ part, size_t ps, int S,
                            float* __restrict__ out, int n4) {
    int i = blockIdx.x * 256 + threadIdx.x;
    if (i >= n4) return;
    const size_t b = (size_t)i * 4;
    float4 a = *(const float4*)(part + b);
    for (int s = 1; s < S; s++) {
        const float4 p = *(const float4*)(part + (size_t)s * ps + b);
        a.x += p.x; a.y += p.y; a.z += p.z; a.w += p.w;
    }
    *(float4*)(out + b) = a;
}

__global__ void reduce_bias(const float* __restrict__ part, size_t ps, int S,
                            const float* __restrict__ bias, float* __restrict__ out,
                            int n4, int N) {
    int i = blockIdx.x * 256 + threadIdx.x;
    if (i >= n4) return;
    const size_t b = (size_t)i * 4;
    float4 a = *(const float4*)(part + b);
    for (int s = 1; s < S; s++) {
        const float4 p = *(const float4*)(part + (size_t)s * ps + b);
        a.x += p.x; a.y += p.y; a.z += p.z; a.w += p.w;
    }
    const float4 bb = *(const float4*)(bias + (int)(b % N));
    a.x += bb.x; a.y += bb.y; a.z += bb.z; a.w += bb.w;
    *(float4*)(out + b) = a;
}

__global__ void reduce_res(const float* __restrict__ part, size_t ps, int S,
                           const float* __restrict__ bias, float* __restrict__ h,
                           int n4, int N) {
    int i = blockIdx.x * 256 + threadIdx.x;
    if (i >= n4) return;
    const size_t b = (size_t)i * 4;
    float4 a = *(const float4*)(part + b);
    for (int s = 1; s < S; s++) {
        const float4 p = *(const float4*)(part + (size_t)s * ps + b);
        a.x += p.x; a.y += p.y; a.z += p.z; a.w += p.w;
    }
    const float4 bb = *(const float4*)(bias + (int)(b % N));
    const float4 hh = *(const float4*)(h + b);
    a.x += bb.x + hh.x; a.y += bb.y + hh.y; a.z += bb.z + hh.z; a.w += bb.w + hh.w;
    *(float4*)(h + b) = a;
}

__global__ void reduce_gelu_pair(const float* __restrict__ part, size_t ps, int S,
                                 const float* __restrict__ bias,
                                 bf16* __restrict__ oh, bf16* __restrict__ ol,
                                 int n4, int N) {
    int i = blockIdx.x * 256 + threadIdx.x;
    if (i >= n4) return;
    const size_t b = (size_t)i * 4;
    float4 a = *(const float4*)(part + b);
    for (int s = 1; s < S; s++) {
        const float4 p = *(const float4*)(part + (size_t)s * ps + b);
        a.x += p.x; a.y += p.y; a.z += p.z; a.w += p.w;
    }
    const float4 bb = *(const float4*)(bias + (int)(b % N));
    float v[4] = { a.x + bb.x, a.y + bb.y, a.z + bb.z, a.w + bb.w };
    bf16 hh[4], ll[4];
#pragma unroll
    for (int j = 0; j < 4; j++) {
        const float gv = 0.5f * v[j] * (1.f + erff(v[j] * 0.7071067811865475f));
        hh[j] = __float2bfloat16(gv);
        ll[j] = __float2bfloat16(gv - __bfloat162float(hh[j]));
    }
    *(__nv_bfloat162*)(oh + b)     = __nv_bfloat162(hh[0], hh[1]);
    *(__nv_bfloat162*)(oh + b + 2) = __nv_bfloat162(hh[2], hh[3]);
    *(__nv_bfloat162*)(ol + b)     = __nv_bfloat162(ll[0], ll[1]);
    *(__nv_bfloat162*)(ol + b + 2) = __nv_bfloat162(ll[2], ll[3]);
}

// ---------------- silu(gate)*up + bf16 hi/lo split ----------------
__global__ void silu_mul_quant(const float* __restrict__ GU,
                               bf16* __restrict__ Uh, bf16* __restrict__ Ul)
{
    const int row = blockIdx.x;
    const float* gr = GU + (size_t)row * FF2;
    bf16* uh = Uh + (size_t)row * FF_PAD;
    bf16* ul = Ul + (size_t)row * FF_PAD;
    for (int i = threadIdx.x; i < FF_PAD; i += 256) {
        float v = 0.f;
        if (i < FF_DIM) {
            const float gv = gr[i];
            v = (gv / (1.f + __expf(-gv))) * gr[FF_PAD + i];
        }
        const bf16 h = __float2bfloat16(v);
        uh[i] = h;
        ul[i] = __float2bfloat16(v - __bfloat162float(h));
    }
}

// ---------------- rmsnorm -> bf16 hi/lo ----------------
__global__ void rmsnorm_pair(const float* __restrict__ x, const float* __restrict__ s,
                             bf16* __restrict__ yh, bf16* __restrict__ yl)
{
    const int row = blockIdx.x;
    const float* xr = x + (size_t)row * D_MODEL;
    float sum = 0.f;
    for (int i = threadIdx.x; i < D_MODEL; i += 256) { float v = xr[i]; sum += v * v; }
#pragma unroll
    for (int o = 16; o; o >>= 1) sum += __shfl_xor_sync(~0u, sum, o);
    __shared__ float red[8];
    const int warp = threadIdx.x >> 5, lane = threadIdx.x & 31;
    if (lane == 0) red[warp] = sum;
    __syncthreads();
    if (warp == 0) {
        float v = (lane < 8) ? red[lane] : 0.f;
#pragma unroll
        for (int o = 4; o; o >>= 1) v += __shfl_xor_sync(~0u, v, o);
        if (lane == 0) red[0] = v;
    }
    __syncthreads();
    const float rinv = rsqrtf(red[0] * (1.f / D_MODEL) + EPS_RMS);
    for (int i = threadIdx.x; i < D_MODEL; i += 256) {
        float v = xr[i] * s[i] * rinv;
        bf16 h = __float2bfloat16(v);
        yh[(size_t)row * D_MODEL + i] = h;
        yl[(size_t)row * D_MODEL + i] = __float2bfloat16(v - __bfloat162float(h));
    }
}

// ---------------- windowed attention with fused RoPE -> bf16 hi/lo ----------------
#define ATT_SMEM ((64 * 80 + 64 * 81 + 64 * 80 + 8 * 64) * 4)

__global__ void attn_kernel(const float* __restrict__ qkv, const float* __restrict__ rot,
                            bf16* __restrict__ oh, bf16* __restrict__ ol)
{
    extern __shared__ float sm[];
    float* qs = sm;
    float* ks = qs + 64 * 80;
    float* vs = ks + 64 * 81;
    float* pr = vs + 64 * 80;
    const int w = blockIdx.x, hh = blockIdx.y;
    const int tid = threadIdx.x, lane = tid & 31, warp = tid >> 5;
    const size_t base = (size_t)w * WIN * (3 * D_MODEL) + hh * HD;

    for (int idx = tid; idx < WIN * HALF; idx += 256) {
        const int t = idx / HALF, d = idx % HALF;
        float s, c;
        sincosf(rot[(w * WIN + t) * HALF + d], &s, &c);
        const size_t g = base + (size_t)t * (3 * D_MODEL) + d;
        const float qre = qkv[g],           qim = qkv[g + HALF];
        const float kre = qkv[g + D_MODEL], kim = qkv[g + D_MODEL + HALF];
        qs[t * 80 + d]        = qre * c - qim * s;
        qs[t * 80 + d + HALF] = qre * s + qim * c;
        ks[t * 81 + d]        = kre * c - kim * s;
        ks[t * 81 + d + HALF] = kre * s + kim * c;
    }
    for (int idx = tid; idx < WIN * HD; idx += 256) {
        const int t = idx / HD, d = idx % HD;
        vs[t * 80 + d] = qkv[base + (size_t)t * (3 * D_MODEL) + 2 * D_MODEL + d];
    }
    __syncthreads();

    for (int row = warp; row < WIN; row += 8) {
        const float* qr = qs + row * 80;
        const float* k0 = ks + lane * 81;
        const float* k1 = ks + (lane + 32) * 81;
        float s0 = 0.f, s1 = 0.f;
#pragma unroll
        for (int d = 0; d < HD; d++) { const float q = qr[d]; s0 += q * k0[d]; s1 += q * k1[d]; }
        s0 *= ATT_SCALE; s1 *= ATT_SCALE;
        float mx = fmaxf(s0, s1);
#pragma unroll
        for (int o = 16; o; o >>= 1) mx = fmaxf(mx, __shfl_xor_sync(~0u, mx, o));
        const float e0 = __expf(s0 - mx), e1 = __expf(s1 - mx);
        float sum = e0 + e1;
#pragma unroll
        for (int o = 16; o; o >>= 1) sum += __shfl_xor_sync(~0u, sum, o);
        const float inv = 1.f / sum;
        pr[warp * 64 + lane] = e0 * inv;
        pr[warp * 64 + lane + 32] = e1 * inv;
        __syncwarp();
        float o0 = 0.f, o1 = 0.f, o2 = 0.f;
#pragma unroll 4
        for (int j = 0; j < WIN; j++) {
            const float p = pr[warp * 64 + j];
            const float* vr = vs + j * 80;
            o0 += p * vr[lane];
            o1 += p * vr[lane + 32];
            if (lane < 16) o2 += p * vr[lane + 64];
        }
        const size_t ob = (size_t)(w * WIN + row) * D_MODEL + hh * HD;
        bf16 h;
        h = __float2bfloat16(o0); oh[ob + lane] = h;
        ol[ob + lane] = __float2bfloat16(o0 - __bfloat162float(h));
        h = __float2bfloat16(o1); oh[ob + lane + 32] = h;
        ol[ob + lane + 32] = __float2bfloat16(o1 - __bfloat162float(h));
        if (lane < 16) {
            h = __float2bfloat16(o2); oh[ob + lane + 64] = h;
            ol[ob + lane + 64] = __float2bfloat16(o2 - __bfloat162float(h));
        }
        __syncwarp();
    }
}

// ---------------- host ----------------
extern "C" void kernel_launch(void* const* d_in, const int* in_sizes, int n_in,
                              void* d_out, int out_size)
{
    const float* x      = (const float*)d_in[0];
    const float* rot    = (const float*)d_in[1];
    const float* patchw = (const float*)d_in[3];
    const float* qkvw   = (const float*)d_in[4];
    const float* qkvb   = (const float*)d_in[5];
    const float* projw  = (const float*)d_in[6];
    const float* projb  = (const float*)d_in[7];
    const float* n1s    = (const float*)d_in[8];
    const float* n2s    = (const float*)d_in[9];
    const float* gw     = (const float*)d_in[10];
    const float* gb     = (const float*)d_in[11];
    const float* uw     = (const float*)d_in[12];
    const float* ub     = (const float*)d_in[13];
    const float* dw     = (const float*)d_in[14];
    const float* db     = (const float*)d_in[15];
    const float* lnq    = (const float*)d_in[16];
    const float* f1w    = (const float*)d_in[17];
    const float* f1b    = (const float*)d_in[18];
    const float* f2w    = (const float*)d_in[19];
    const float* f2b    = (const float*)d_in[20];
    float* out = (float*)d_out;

    float *h, *qkv, *gu, *gub, *part;
    bf16 *xh, *xl, *nh, *nl, *ath, *atl, *uph, *upl, *f1h, *f1l;
    bf16 *patchTh, *patchTl, *qkvTh, *qkvTl, *projTh, *projTl;
    bf16 *guTh, *guTl, *downTh, *downTl, *fc1Th, *fc1Tl, *fc2Th, *fc2Tl;
#define GA(p, s) cudaGetSymbolAddress((void**)&p, s)
    GA(h, g_h); GA(qkv, g_qkv); GA(gu, g_gu); GA(gub, g_gub); GA(part, g_part);
    GA(xh, g_xh); GA(xl, g_xl); GA(nh, g_nh); GA(nl, g_nl);
    GA(ath, g_ath); GA(atl, g_atl); GA(uph, g_uph); GA(upl, g_upl);
    GA(f1h, g_f1h); GA(f1l, g_f1l);
    GA(patchTh, g_patchTh); GA(patchTl, g_patchTl);
    GA(qkvTh, g_qkvTh); GA(qkvTl, g_qkvTl);
    GA(projTh, g_projTh); GA(projTl, g_projTl);
    GA(guTh, g_guTh); GA(guTl, g_guTl);
    GA(downTh, g_downTh); GA(downTl, g_downTl);
    GA(fc1Th, g_fc1Th); GA(fc1Tl, g_fc1Tl);
    GA(fc2Th, g_fc2Th); GA(fc2Tl, g_fc2Tl);
#undef GA

    cudaFuncSetAttribute(attn_kernel, cudaFuncAttributeMaxDynamicSharedMemorySize, ATT_SMEM);
    cudaFuncSetAttribute(gemm_bias, cudaFuncAttributeMaxDynamicSharedMemorySize, GEMM_SMEM);
    cudaFuncSetAttribute(gemm_part, cudaFuncAttributeMaxDynamicSharedMemorySize, GEMM_SMEM);

    // ---- setup: splits + weight conversion ----
    conv_act<<<(T_TOK * PATCH_KP + 255) / 256, 256>>>(x, xh, xl, T_TOK, PATCH_IN, PATCH_KP);
    build_gub<<<(DEPTH * FF2 + 255) / 256, 256>>>(gb, ub);
    {
        ConvTable tb;
        int tc = 0, si = 0;
        auto add = [&](const float* s, bf16* dh, bf16* dl, int K, int N, int Kp, int Np) {
            const int tx = (Kp + 31) / 32, ty = (Np + 31) / 32;
            tb.seg[si] = { s, dh, dl, K, N, Kp, tc, tx };
            tc += tx * ty; si++;
        };
        add(patchw, patchTh, patchTl, PATCH_IN, 1280, PATCH_KP, 1280);
        for (int l = 0; l < DEPTH; l++) {
            add(qkvw + (size_t)l * 1280 * 3840, qkvTh + (size_t)l * 3840 * 1280,
                qkvTl + (size_t)l * 3840 * 1280, 1280, 3840, 1280, 3840);
            add(projw + (size_t)l * 1280 * 1280, projTh + (size_t)l * 1280 * 1280,
                projTl + (size_t)l * 1280 * 1280, 1280, 1280, 1280, 1280);
            add(gw + (size_t)l * 1280 * FF_DIM, guTh + (size_t)l * FF2 * 1280,
                guTl + (size_t)l * FF2 * 1280, 1280, FF_DIM, 1280, FF_PAD);
            add(uw + (size_t)l * 1280 * FF_DIM,
                guTh + (size_t)l * FF2 * 1280 + (size_t)FF_PAD * 1280,
                guTl + (size_t)l * FF2 * 1280 + (size_t)FF_PAD * 1280,
                1280, FF_DIM, 1280, FF_PAD);
            add(dw + (size_t)l * FF_DIM * 1280, downTh + (size_t)l * 1280 * FF_PAD,
                downTl + (size_t)l * 1280 * FF_PAD, FF_DIM, 1280, FF_PAD, 1280);
        }
        add(f1w, fc1Th, fc1Tl, 5120, 5120, 5120, 5120);
        add(f2w, fc2Th, fc2Tl, 5120, 3584, 5120, 3584);
        conv_all<<<tc, dim3(32, 8)>>>(tb);
    }

    const size_t psD = (size_t)T_TOK * D_MODEL;        // 2048x1280 partial stride
    const size_t psQ = (size_t)T_TOK * 3 * D_MODEL;    // 2048x3840
    const size_t psF = (size_t)512 * 5120;             // 512x5120
    const int n4D = T_TOK * D_MODEL / 4;
    const int n4Q = T_TOK * 3 * D_MODEL / 4;
    const int n4F = 512 * 5120 / 4;

    // ---- patch embed: split-K4 + reduce ----
    gemm_part<<<dim3(16, 10, 4), 256, GEMM_SMEM>>>(
        xh, xl, patchTh, patchTl, part, psD, PATCH_KP, 1280);
    reduce_none<<<(n4D + 255) / 256, 256>>>(part, psD, 4, h, n4D);

    for (int l = 0; l < DEPTH; l++) {
        const size_t lD = (size_t)l * D_MODEL;
        rmsnorm_pair<<<T_TOK, 256>>>(h, n1s + lD, nh, nl);
        // qkv: split-K2
        gemm_part<<<dim3(16, 30, 2), 256, GEMM_SMEM>>>(
            nh, nl, qkvTh + (size_t)l * 3840 * 1280, qkvTl + (size_t)l * 3840 * 1280,
            part, psQ, 1280, 3840);
        reduce_bias<<<(n4Q + 255) / 256, 256>>>(part, psQ, 2,
            qkvb + (size_t)l * 3840, qkv, n4Q, 3840);
        attn_kernel<<<dim3(NWIN, H_HEADS), 256, ATT_SMEM>>>(qkv, rot, ath, atl);
        // proj: split-K4, residual+bias in reduce
        gemm_part<<<dim3(16, 10, 4), 256, GEMM_SMEM>>>(
            ath, atl, projTh + (size_t)l * 1280 * 1280, projTl + (size_t)l * 1280 * 1280,
            part, psD, 1280, 1280);
        reduce_res<<<(n4D + 255) / 256, 256>>>(part, psD, 4, projb + lD, h, n4D, 1280);
        rmsnorm_pair<<<T_TOK, 256>>>(h, n2s + lD, nh, nl);
        // fused gate|up GEMM (N = 6912), bias fused
        gemm_bias<<<dim3(16, FF2 / 128), 256, GEMM_SMEM>>>(
            nh, nl, guTh + (size_t)l * FF2 * 1280, guTl + (size_t)l * FF2 * 1280,
            gub + (size_t)l * FF2, gu, 1280, FF2);
        silu_mul_quant<<<T_TOK, 256>>>(gu, uph, upl);
        // down: split-K4, residual+bias in reduce
        gemm_part<<<dim3(16, 10, 4), 256, GEMM_SMEM>>>(
            uph, upl, downTh + (size_t)l * 1280 * FF_PAD, downTl + (size_t)l * 1280 * FF_PAD,
            part, psD, FF_PAD, 1280);
        reduce_res<<<(n4D + 255) / 256, 256>>>(part, psD, 4, db + lD, h, n4D, 1280);
    }

    // ---- merger ----
    rmsnorm_pair<<<T_TOK, 256>>>(h, lnq, nh, nl);           // viewed as [512, 5120]
    // fc1: split-K8 + gelu/pair reduce
    gemm_part<<<dim3(4, 40, 8), 256, GEMM_SMEM>>>(
        nh, nl, fc1Th, fc1Tl, part, psF, 5120, 5120);
    reduce_gelu_pair<<<(n4F + 255) / 256, 256>>>(part, psF, 8, f1b, f1h, f1l, n4F, 5120);
    // fc2: single-phase fused bias
    gemm_bias<<<dim3(4, 28), 256, GEMM_SMEM>>>(
        f1h, f1l, fc2Th, fc2Tl, f2b, out, 5120, 3584);
}

// round 9
// speedup vs baseline: 3.1554x; 1.0923x over previous
#include <cuda_runtime.h>
#include <cuda_bf16.h>
#include <math.h>
#include <stdint.h>

// ---------------- problem constants ----------------
#define T_TOK   2048
#define D_MODEL 1280
#define H_HEADS 16
#define HD      80
#define HALF    40
#define FF_DIM  3420
#define FF_PAD  3456
#define FF2     (2 * FF_PAD)          // 6912 fused gate|up
#define DEPTH   4
#define OUT_DIM 3584
#define PATCH_IN 1176
#define PATCH_KP 1216
#define WIN     64
#define NWIN    (T_TOK / WIN)
#define EPS_RMS 1e-6f
#define ATT_SCALE 0.1118033988749895f

typedef __nv_bfloat16 bf16;

// ---------------- helpers ----------------
__device__ __forceinline__ uint32_t smem_u32(const void* p) {
    uint32_t a;
    asm("{ .reg .u64 t; cvta.to.shared.u64 t, %1; cvt.u32.u64 %0, t; }" : "=r"(a) : "l"(p));
    return a;
}
__device__ __forceinline__ void cp_async16(uint32_t s, const void* g) {
    asm volatile("cp.async.cg.shared.global [%0], [%1], 16;" :: "r"(s), "l"(g));
}
#define CP_COMMIT() asm volatile("cp.async.commit_group;" ::: "memory")
#define CP_WAIT(n)  asm volatile("cp.async.wait_group %0;" :: "n"(n) : "memory")

__device__ __forceinline__ void ldm_x4(uint32_t& r0, uint32_t& r1, uint32_t& r2,
                                       uint32_t& r3, uint32_t addr) {
    asm volatile("ldmatrix.sync.aligned.m8n8.x4.shared.b16 {%0,%1,%2,%3}, [%4];"
                 : "=r"(r0), "=r"(r1), "=r"(r2), "=r"(r3) : "r"(addr));
}
__device__ __forceinline__ void mma16816(float* d, const uint32_t* a,
                                         uint32_t b0, uint32_t b1) {
    asm volatile("mma.sync.aligned.m16n8k16.row.col.f32.bf16.bf16.f32 "
                 "{%0,%1,%2,%3}, {%4,%5,%6,%7}, {%8,%9}, {%0,%1,%2,%3};"
                 : "+f"(d[0]), "+f"(d[1]), "+f"(d[2]), "+f"(d[3])
                 : "r"(a[0]), "r"(a[1]), "r"(a[2]), "r"(a[3]), "r"(b0), "r"(b1));
}
// swizzled smem byte offset: 64B rows, 16B segs, XOR key (row>>1)&3 (bank-conflict-free)
__device__ __forceinline__ uint32_t swz(int row, int seg) {
    return (uint32_t)(row * 64 + ((seg ^ ((row >> 1) & 3)) << 4));
}

// ---------------- scratch ----------------
__device__ float g_h  [T_TOK * D_MODEL];
__device__ float g_gu [(size_t)T_TOK * FF2];
__device__ float g_gub[DEPTH * FF2];
__device__ float g_part[(size_t)8 * 512 * 5120];   // split-K partials (max: fc1 S=8, qkv S=2)
__device__ bf16  g_xh [T_TOK * PATCH_KP],       g_xl [T_TOK * PATCH_KP];
__device__ bf16  g_nh [T_TOK * D_MODEL],        g_nl [T_TOK * D_MODEL];
__device__ bf16  g_ath[T_TOK * D_MODEL],        g_atl[T_TOK * D_MODEL];
__device__ bf16  g_uph[(size_t)T_TOK * FF_PAD], g_upl[(size_t)T_TOK * FF_PAD];
__device__ bf16  g_f1h[512 * 4 * D_MODEL],      g_f1l[512 * 4 * D_MODEL];
// transposed/split weights [N, Kp]
__device__ bf16 g_patchTh[1280 * PATCH_KP],              g_patchTl[1280 * PATCH_KP];
__device__ bf16 g_qkvTh [DEPTH * 3840 * 1280],           g_qkvTl [DEPTH * 3840 * 1280];
__device__ bf16 g_projTh[DEPTH * 1280 * 1280],           g_projTl[DEPTH * 1280 * 1280];
__device__ bf16 g_guTh  [(size_t)DEPTH * FF2 * 1280],    g_guTl  [(size_t)DEPTH * FF2 * 1280];
__device__ bf16 g_downTh[(size_t)DEPTH * 1280 * FF_PAD], g_downTl[(size_t)DEPTH * 1280 * FF_PAD];
__device__ bf16 g_fc1Th [5120 * 5120],                   g_fc1Tl [5120 * 5120];
__device__ bf16 g_fc2Th [3584 * 5120],                   g_fc2Tl [3584 * 5120];

// ---------------- activation split ----------------
__global__ void conv_act(const float* __restrict__ X, bf16* __restrict__ Xh,
                         bf16* __restrict__ Xl, int M, int K, int Kp) {
    int idx = blockIdx.x * 256 + threadIdx.x;
    if (idx >= M * Kp) return;
    int m = idx / Kp, k = idx - m * Kp;
    float v = (k < K) ? X[(size_t)m * K + k] : 0.f;
    bf16 h = __float2bfloat16(v);
    Xh[idx] = h;
    Xl[idx] = __float2bfloat16(v - __bfloat162float(h));
}

// ---------------- concat bias builder ----------------
__global__ void build_gub(const float* __restrict__ gb, const float* __restrict__ ub) {
    int idx = blockIdx.x * 256 + threadIdx.x;
    if (idx >= DEPTH * FF2) return;
    const int l = idx / FF2, c = idx - l * FF2;
    float v = 0.f;
    if (c < FF_DIM)                              v = gb[l * FF_DIM + c];
    else if (c >= FF_PAD && c < FF_PAD + FF_DIM) v = ub[l * FF_DIM + (c - FF_PAD)];
    g_gub[idx] = v;
}

// ---------------- batched weight transpose+split ----------------
#define NSEG 23
struct Seg { const float* s; bf16* dh; bf16* dl; int K, N, Kp, tile0, tilesX; };
struct ConvTable { Seg seg[NSEG]; };

__global__ void conv_all(ConvTable tb) {
    __shared__ float t[32][33];
    const int tile = blockIdx.x;
    int si = 0;
#pragma unroll
    for (int i = 1; i < NSEG; i++) si += (tb.seg[i].tile0 <= tile);
    const Seg sg = tb.seg[si];
    const int lt = tile - sg.tile0;
    const int kb = (lt % sg.tilesX) * 32;
    const int nb = (lt / sg.tilesX) * 32;
#pragma unroll
    for (int j = 0; j < 32; j += 8) {
        int k = kb + threadIdx.y + j, n = nb + threadIdx.x;
        t[threadIdx.y + j][threadIdx.x] =
            (k < sg.K && n < sg.N) ? sg.s[(size_t)k * sg.N + n] : 0.f;
    }
    __syncthreads();
#pragma unroll
    for (int j = 0; j < 32; j += 8) {
        int n = nb + threadIdx.y + j, k = kb + threadIdx.x;
        if (k < sg.Kp) {
            float v = t[threadIdx.x][threadIdx.y + j];
            bf16 h = __float2bfloat16(v);
            sg.dh[(size_t)n * sg.Kp + k] = h;
            sg.dl[(size_t)n * sg.Kp + k] = __float2bfloat16(v - __bfloat162float(h));
        }
    }
}

// ---------------- GEMM machinery: 128x128 tile, swizzled 64B rows, 6 stages ----------------
#define NSTAGE 6
#define STAGE_BYTES (256 * 64)            // A 128 rows + B 128 rows, 64B each
#define GEMM_SMEM (NSTAGE * STAGE_BYTES)  // 98304

// mainloop body shared by both kernels via macro (pair-processed, 1 sync / 2 chunks)
#define GEMM_MAINLOOP(C0, C1)                                                      \
    loadChunk(C0 + 0, 0); loadChunk(C0 + 1, 1);                                    \
    loadChunk(C0 + 2, 2); loadChunk(C0 + 3, 3);                                    \
    for (int c = C0; c < C1; c += 2) {                                             \
        if (c + 2 < C1) { CP_WAIT(2); } else { CP_WAIT(0); }                       \
        __syncthreads();                                                           \
        if (c + 4 < C1) loadChunk(c + 4, (c + 4 - C0) % NSTAGE);                   \
        if (c + 5 < C1) loadChunk(c + 5, (c + 5 - C0) % NSTAGE);                   \
        computeChunk((c - C0) % NSTAGE);                                           \
        computeChunk((c + 1 - C0) % NSTAGE);                                       \
    }

// ---- full GEMM with fused bias (gu, fc2; N multiple of 128) ----
__global__ __launch_bounds__(256, 2)
void gemm_bias(const bf16* __restrict__ Ah, const bf16* __restrict__ Al,
               const bf16* __restrict__ Bh, const bf16* __restrict__ Bl,
               const float* __restrict__ bias, float* __restrict__ C,
               int Kp, int N)
{
    extern __shared__ __align__(128) char smem[];
    const uint32_t sbase = smem_u32(smem);
    const int tid = threadIdx.x, lane = tid & 31, wid = tid >> 5;
    const int warp_m = wid >> 2, warp_n = wid & 3;
    const int row0 = blockIdx.x * 128, col0 = blockIdx.y * 128;

    const int kc  = Kp >> 5;
    const int nch = 3 * kc;
    const size_t rowB = (size_t)Kp * 2;
    const int ld_r = tid >> 2;
    const int ld_s = tid & 3;

    auto loadChunk = [&](int c, int buf) {
        const int p = c / kc;
        const size_t kk = (size_t)(c - p * kc) * 64;
        const char* Ap = (const char*)(p == 2 ? Al : Ah) + (size_t)row0 * rowB + kk;
        const char* Bp = (const char*)(p == 1 ? Bl : Bh) + (size_t)col0 * rowB + kk;
        const uint32_t sA = sbase + buf * STAGE_BYTES;
        const uint32_t sB = sA + 128 * 64;
#pragma unroll
        for (int i = 0; i < 2; i++) {
            const int r = ld_r + i * 64;
            cp_async16(sA + swz(r, ld_s), Ap + (size_t)r * rowB + ld_s * 16);
            cp_async16(sB + swz(r, ld_s), Bp + (size_t)r * rowB + ld_s * 16);
        }
        CP_COMMIT();
    };

    float acc[4][4][4];
#pragma unroll
    for (int i = 0; i < 4; i++)
#pragma unroll
        for (int j = 0; j < 4; j++)
#pragma unroll
            for (int q = 0; q < 4; q++) acc[i][j][q] = 0.f;

    const int a_row = warp_m * 64 + (lane & 15);
    const int a_seg = (lane >> 4);
    const int b_row = warp_n * 32 + (lane & 7) + ((lane >> 4) << 3);
    const int b_seg = (lane >> 3) & 1;

    auto computeChunk = [&](int buf) {
        const uint32_t sA = sbase + buf * STAGE_BYTES;
        const uint32_t sB = sA + 128 * 64;
#pragma unroll
        for (int s = 0; s < 2; s++) {
            uint32_t a[4][4], b[2][4];
#pragma unroll
            for (int mi = 0; mi < 4; mi++)
                ldm_x4(a[mi][0], a[mi][1], a[mi][2], a[mi][3],
                       sA + swz(a_row + mi * 16, s * 2 + a_seg));
#pragma unroll
            for (int j = 0; j < 2; j++)
                ldm_x4(b[j][0], b[j][1], b[j][2], b[j][3],
                       sB + swz(b_row + j * 16, s * 2 + b_seg));
#pragma unroll
            for (int mi = 0; mi < 4; mi++)
#pragma unroll
                for (int ni = 0; ni < 4; ni++)
                    mma16816(acc[mi][ni], a[mi],
                             b[ni >> 1][(ni & 1) * 2], b[ni >> 1][(ni & 1) * 2 + 1]);
        }
    };

    GEMM_MAINLOOP(0, nch)

    const int g = lane >> 2, tig = lane & 3;
#pragma unroll
    for (int mi = 0; mi < 4; mi++)
#pragma unroll
        for (int half = 0; half < 2; half++) {
            const int r = row0 + warp_m * 64 + mi * 16 + g + half * 8;
#pragma unroll
            for (int ni = 0; ni < 4; ni++) {
                const int col = col0 + warp_n * 32 + ni * 8 + tig * 2;
                const float2 bb = *(const float2*)(bias + col);
                *(float2*)(C + (size_t)r * N + col) =
                    make_float2(acc[mi][ni][half * 2 + 0] + bb.x,
                                acc[mi][ni][half * 2 + 1] + bb.y);
            }
        }
}

// ---- split-K GEMM: writes raw partials (grid.z = split index) ----
__global__ __launch_bounds__(256, 2)
void gemm_part(const bf16* __restrict__ Ah, const bf16* __restrict__ Al,
               const bf16* __restrict__ Bh, const bf16* __restrict__ Bl,
               float* __restrict__ part, size_t pstride,
               int Kp, int N)
{
    extern __shared__ __align__(128) char smem[];
    const uint32_t sbase = smem_u32(smem);
    const int tid = threadIdx.x, lane = tid & 31, wid = tid >> 5;
    const int warp_m = wid >> 2, warp_n = wid & 3;
    const int row0 = blockIdx.x * 128, col0 = blockIdx.y * 128;
    const int S = gridDim.z, sidx = blockIdx.z;

    const int kc  = Kp >> 5;
    const int nch = 3 * kc;
    const int npair = nch >> 1;
    const int c0 = 2 * ((sidx * npair) / S);
    const int c1 = 2 * (((sidx + 1) * npair) / S);
    const size_t rowB = (size_t)Kp * 2;
    const int ld_r = tid >> 2;
    const int ld_s = tid & 3;

    auto loadChunk = [&](int c, int buf) {
        const int p = c / kc;
        const size_t kk = (size_t)(c - p * kc) * 64;
        const char* Ap = (const char*)(p == 2 ? Al : Ah) + (size_t)row0 * rowB + kk;
        const char* Bp = (const char*)(p == 1 ? Bl : Bh) + (size_t)col0 * rowB + kk;
        const uint32_t sA = sbase + buf * STAGE_BYTES;
        const uint32_t sB = sA + 128 * 64;
#pragma unroll
        for (int i = 0; i < 2; i++) {
            const int r = ld_r + i * 64;
            cp_async16(sA + swz(r, ld_s), Ap + (size_t)r * rowB + ld_s * 16);
            cp_async16(sB + swz(r, ld_s), Bp + (size_t)r * rowB + ld_s * 16);
        }
        CP_COMMIT();
    };

    float acc[4][4][4];
#pragma unroll
    for (int i = 0; i < 4; i++)
#pragma unroll
        for (int j = 0; j < 4; j++)
#pragma unroll
            for (int q = 0; q < 4; q++) acc[i][j][q] = 0.f;

    const int a_row = warp_m * 64 + (lane & 15);
    const int a_seg = (lane >> 4);
    const int b_row = warp_n * 32 + (lane & 7) + ((lane >> 4) << 3);
    const int b_seg = (lane >> 3) & 1;

    auto computeChunk = [&](int buf) {
        const uint32_t sA = sbase + buf * STAGE_BYTES;
        const uint32_t sB = sA + 128 * 64;
#pragma unroll
        for (int s = 0; s < 2; s++) {
            uint32_t a[4][4], b[2][4];
#pragma unroll
            for (int mi = 0; mi < 4; mi++)
                ldm_x4(a[mi][0], a[mi][1], a[mi][2], a[mi][3],
                       sA + swz(a_row + mi * 16, s * 2 + a_seg));
#pragma unroll
            for (int j = 0; j < 2; j++)
                ldm_x4(b[j][0], b[j][1], b[j][2], b[j][3],
                       sB + swz(b_row + j * 16, s * 2 + b_seg));
#pragma unroll
            for (int mi = 0; mi < 4; mi++)
#pragma unroll
                for (int ni = 0; ni < 4; ni++)
                    mma16816(acc[mi][ni], a[mi],
                             b[ni >> 1][(ni & 1) * 2], b[ni >> 1][(ni & 1) * 2 + 1]);
        }
    };

    GEMM_MAINLOOP(c0, c1)

    float* P = part + (size_t)sidx * pstride;
    const int g = lane >> 2, tig = lane & 3;
#pragma unroll
    for (int mi = 0; mi < 4; mi++)
#pragma unroll
        for (int half = 0; half < 2; half++) {
            const int r = row0 + warp_m * 64 + mi * 16 + g + half * 8;
#pragma unroll
            for (int ni = 0; ni < 4; ni++) {
                const int col = col0 + warp_n * 32 + ni * 8 + tig * 2;
                *(float2*)(P + (size_t)r * N + col) =
                    make_float2(acc[mi][ni][half * 2 + 0], acc[mi][ni][half * 2 + 1]);
            }
        }
}

// ---------------- fused split-K reduce (+bias,+residual) + rmsnorm -> bf16 hi/lo ----------------
template <bool RES>
__global__ void reduce_rms(const float* __restrict__ part, size_t ps, int S,
                           const float* __restrict__ bias, const float* __restrict__ scale,
                           float* __restrict__ h, bf16* __restrict__ yh, bf16* __restrict__ yl)
{
    const int row = blockIdx.x;
    const size_t rb = (size_t)row * D_MODEL;
    float v[5];
    float sumsq = 0.f;
#pragma unroll
    for (int j = 0; j < 5; j++) {
        const int i = threadIdx.x + j * 256;
        float val = part[rb + i];
        for (int s = 1; s < S; s++) val += part[(size_t)s * ps + rb + i];
        if (RES) val += bias[i] + h[rb + i];
        h[rb + i] = val;
        v[j] = val;
        sumsq += val * val;
    }
#pragma unroll
    for (int o = 16; o; o >>= 1) sumsq += __shfl_xor_sync(~0u, sumsq, o);
    __shared__ float red[8];
    const int warp = threadIdx.x >> 5, lane = threadIdx.x & 31;
    if (lane == 0) red[warp] = sumsq;
    __syncthreads();
    if (warp == 0) {
        float t = (lane < 8) ? red[lane] : 0.f;
#pragma unroll
        for (int o = 4; o; o >>= 1) t += __shfl_xor_sync(~0u, t, o);
        if (lane == 0) red[0] = t;
    }
    __syncthreads();
    const float rinv = rsqrtf(red[0] * (1.f / D_MODEL) + EPS_RMS);
#pragma unroll
    for (int j = 0; j < 5; j++) {
        const int i = threadIdx.x + j * 256;
        const float y = v[j] * scale[i] * rinv;
        const bf16 hh = __float2bfloat16(y);
        yh[rb + i] = hh;
        yl[rb + i] = __float2bfloat16(y - __bfloat162float(hh));
    }
}

// ---------------- fc1 reduce: +bias, gelu, pair split ----------------
__global__ void reduce_gelu_pair(const float* __restrict__ part, size_t ps, int S,
                                 const float* __restrict__ bias,
                                 bf16* __restrict__ oh, bf16* __restrict__ ol,
                                 int n4, int N) {
    int i = blockIdx.x * 256 + threadIdx.x;
    if (i >= n4) return;
    const size_t b = (size_t)i * 4;
    float4 a = *(const float4*)(part + b);
    for (int s = 1; s < S; s++) {
        const float4 p = *(const float4*)(part + (size_t)s * ps + b);
        a.x += p.x; a.y += p.y; a.z += p.z; a.w += p.w;
    }
    const float4 bb = *(const float4*)(bias + (int)(b % N));
    float v[4] = { a.x + bb.x, a.y + bb.y, a.z + bb.z, a.w + bb.w };
    bf16 hh[4], ll[4];
#pragma unroll
    for (int j = 0; j < 4; j++) {
        const float gv = 0.5f * v[j] * (1.f + erff(v[j] * 0.7071067811865475f));
        hh[j] = __float2bfloat16(gv);
        ll[j] = __float2bfloat16(gv - __bfloat162float(hh[j]));
    }
    *(__nv_bfloat162*)(oh + b)     = __nv_bfloat162(hh[0], hh[1]);
    *(__nv_bfloat162*)(oh + b + 2) = __nv_bfloat162(hh[2], hh[3]);
    *(__nv_bfloat162*)(ol + b)     = __nv_bfloat162(ll[0], ll[1]);
    *(__nv_bfloat162*)(ol + b + 2) = __nv_bfloat162(ll[2], ll[3]);
}

// ---------------- silu(gate)*up + bf16 hi/lo split ----------------
__global__ void silu_mul_quant(const float* __restrict__ GU,
                               bf16* __restrict__ Uh, bf16* __restrict__ Ul)
{
    const int row = blockIdx.x;
    const float* gr = GU + (size_t)row * FF2;
    bf16* uh = Uh + (size_t)row * FF_PAD;
    bf16* ul = Ul + (size_t)row * FF_PAD;
    for (int i = threadIdx.x; i < FF_PAD; i += 256) {
        float v = 0.f;
        if (i < FF_DIM) {
            const float gv = gr[i];
            v = (gv / (1.f + __expf(-gv))) * gr[FF_PAD + i];
        }
        const bf16 h = __float2bfloat16(v);
        uh[i] = h;
        ul[i] = __float2bfloat16(v - __bfloat162float(h));
    }
}

// ---------------- attention: fused qkv split-K(S=2) reduce + bias + RoPE ----------------
#define ATT_SMEM ((64 * 80 + 64 * 81 + 64 * 80 + 8 * 64) * 4)

__global__ void attn_kernel(const float* __restrict__ part, size_t ps,
                            const float* __restrict__ qkvb,
                            const float* __restrict__ rot,
                            bf16* __restrict__ oh, bf16* __restrict__ ol)
{
    extern __shared__ float sm[];
    float* qs = sm;
    float* ks = qs + 64 * 80;
    float* vs = ks + 64 * 81;
    float* pr = vs + 64 * 80;
    const int w = blockIdx.x, hh = blockIdx.y;
    const int tid = threadIdx.x, lane = tid & 31, warp = tid >> 5;
    const size_t base = (size_t)w * WIN * (3 * D_MODEL) + hh * HD;
    const int cb = hh * HD;          // bias col base for q

    for (int idx = tid; idx < WIN * HALF; idx += 256) {
        const int t = idx / HALF, d = idx % HALF;
        float s, c;
        sincosf(rot[(w * WIN + t) * HALF + d], &s, &c);
        const size_t g = base + (size_t)t * (3 * D_MODEL) + d;
        const float qre = part[g] + part[ps + g] + qkvb[cb + d];
        const float qim = part[g + HALF] + part[ps + g + HALF] + qkvb[cb + d + HALF];
        const float kre = part[g + D_MODEL] + part[ps + g + D_MODEL] + qkvb[cb + d + D_MODEL];
        const float kim = part[g + D_MODEL + HALF] + part[ps + g + D_MODEL + HALF]
                        + qkvb[cb + d + D_MODEL + HALF];
        qs[t * 80 + d]        = qre * c - qim * s;
        qs[t * 80 + d + HALF] = qre * s + qim * c;
        ks[t * 81 + d]        = kre * c - kim * s;
        ks[t * 81 + d + HALF] = kre * s + kim * c;
    }
    for (int idx = tid; idx < WIN * HD; idx += 256) {
        const int t = idx / HD, d = idx % HD;
        const size_t g = base + (size_t)t * (3 * D_MODEL) + 2 * D_MODEL + d;
        vs[t * 80 + d] = part[g] + part[ps + g] + qkvb[cb + d + 2 * D_MODEL];
    }
    __syncthreads();

    for (int row = warp; row < WIN; row += 8) {
        const float* qr = qs + row * 80;
        const float* k0 = ks + lane * 81;
        const float* k1 = ks + (lane + 32) * 81;
        float s0 = 0.f, s1 = 0.f;
#pragma unroll
        for (int d = 0; d < HD; d++) { const float q = qr[d]; s0 += q * k0[d]; s1 += q * k1[d]; }
        s0 *= ATT_SCALE; s1 *= ATT_SCALE;
        float mx = fmaxf(s0, s1);
#pragma unroll
        for (int o = 16; o; o >>= 1) mx = fmaxf(mx, __shfl_xor_sync(~0u, mx, o));
        const float e0 = __expf(s0 - mx), e1 = __expf(s1 - mx);
        float sum = e0 + e1;
#pragma unroll
        for (int o = 16; o; o >>= 1) sum += __shfl_xor_sync(~0u, sum, o);
        const float inv = 1.f / sum;
        pr[warp * 64 + lane] = e0 * inv;
        pr[warp * 64 + lane + 32] = e1 * inv;
        __syncwarp();
        float o0 = 0.f, o1 = 0.f, o2 = 0.f;
#pragma unroll 4
        for (int j = 0; j < WIN; j++) {
            const float p = pr[warp * 64 + j];
            const float* vr = vs + j * 80;
            o0 += p * vr[lane];
            o1 += p * vr[lane + 32];
            if (lane < 16) o2 += p * vr[lane + 64];
        }
        const size_t ob = (size_t)(w * WIN + row) * D_MODEL + hh * HD;
        bf16 h;
        h = __float2bfloat16(o0); oh[ob + lane] = h;
        ol[ob + lane] = __float2bfloat16(o0 - __bfloat162float(h));
        h = __float2bfloat16(o1); oh[ob + lane + 32] = h;
        ol[ob + lane + 32] = __float2bfloat16(o1 - __bfloat162float(h));
        if (lane < 16) {
            h = __float2bfloat16(o2); oh[ob + lane + 64] = h;
            ol[ob + lane + 64] = __float2bfloat16(o2 - __bfloat162float(h));
        }
        __syncwarp();
    }
}

// ---------------- host ----------------
extern "C" void kernel_launch(void* const* d_in, const int* in_sizes, int n_in,
                              void* d_out, int out_size)
{
    const float* x      = (const float*)d_in[0];
    const float* rot    = (const float*)d_in[1];
    const float* patchw = (const float*)d_in[3];
    const float* qkvw   = (const float*)d_in[4];
    const float* qkvb   = (const float*)d_in[5];
    const float* projw  = (const float*)d_in[6];
    const float* projb  = (const float*)d_in[7];
    const float* n1s    = (const float*)d_in[8];
    const float* n2s    = (const float*)d_in[9];
    const float* gw     = (const float*)d_in[10];
    const float* gb     = (const float*)d_in[11];
    const float* uw     = (const float*)d_in[12];
    const float* ub     = (const float*)d_in[13];
    const float* dw     = (const float*)d_in[14];
    const float* db     = (const float*)d_in[15];
    const float* lnq    = (const float*)d_in[16];
    const float* f1w    = (const float*)d_in[17];
    const float* f1b    = (const float*)d_in[18];
    const float* f2w    = (const float*)d_in[19];
    const float* f2b    = (const float*)d_in[20];
    float* out = (float*)d_out;

    float *h, *gu, *gub, *part;
    bf16 *xh, *xl, *nh, *nl, *ath, *atl, *uph, *upl, *f1h, *f1l;
    bf16 *patchTh, *patchTl, *qkvTh, *qkvTl, *projTh, *projTl;
    bf16 *guTh, *guTl, *downTh, *downTl, *fc1Th, *fc1Tl, *fc2Th, *fc2Tl;
#define GA(p, s) cudaGetSymbolAddress((void**)&p, s)
    GA(h, g_h); GA(gu, g_gu); GA(gub, g_gub); GA(part, g_part);
    GA(xh, g_xh); GA(xl, g_xl); GA(nh, g_nh); GA(nl, g_nl);
    GA(ath, g_ath); GA(atl, g_atl); GA(uph, g_uph); GA(upl, g_upl);
    GA(f1h, g_f1h); GA(f1l, g_f1l);
    GA(patchTh, g_patchTh); GA(patchTl, g_patchTl);
    GA(qkvTh, g_qkvTh); GA(qkvTl, g_qkvTl);
    GA(projTh, g_projTh); GA(projTl, g_projTl);
    GA(guTh, g_guTh); GA(guTl, g_guTl);
    GA(downTh, g_downTh); GA(downTl, g_downTl);
    GA(fc1Th, g_fc1Th); GA(fc1Tl, g_fc1Tl);
    GA(fc2Th, g_fc2Th); GA(fc2Tl, g_fc2Tl);
#undef GA

    cudaFuncSetAttribute(attn_kernel, cudaFuncAttributeMaxDynamicSharedMemorySize, ATT_SMEM);
    cudaFuncSetAttribute(gemm_bias, cudaFuncAttributeMaxDynamicSharedMemorySize, GEMM_SMEM);
    cudaFuncSetAttribute(gemm_part, cudaFuncAttributeMaxDynamicSharedMemorySize, GEMM_SMEM);

    // ---- setup: splits + weight conversion ----
    conv_act<<<(T_TOK * PATCH_KP + 255) / 256, 256>>>(x, xh, xl, T_TOK, PATCH_IN, PATCH_KP);
    build_gub<<<(DEPTH * FF2 + 255) / 256, 256>>>(gb, ub);
    {
        ConvTable tb;
        int tc = 0, si = 0;
        auto add = [&](const float* s, bf16* dh, bf16* dl, int K, int N, int Kp, int Np) {
            const int tx = (Kp + 31) / 32, ty = (Np + 31) / 32;
            tb.seg[si] = { s, dh, dl, K, N, Kp, tc, tx };
            tc += tx * ty; si++;
        };
        add(patchw, patchTh, patchTl, PATCH_IN, 1280, PATCH_KP, 1280);
        for (int l = 0; l < DEPTH; l++) {
            add(qkvw + (size_t)l * 1280 * 3840, qkvTh + (size_t)l * 3840 * 1280,
                qkvTl + (size_t)l * 3840 * 1280, 1280, 3840, 1280, 3840);
            add(projw + (size_t)l * 1280 * 1280, projTh + (size_t)l * 1280 * 1280,
                projTl + (size_t)l * 1280 * 1280, 1280, 1280, 1280, 1280);
            add(gw + (size_t)l * 1280 * FF_DIM, guTh + (size_t)l * FF2 * 1280,
                guTl + (size_t)l * FF2 * 1280, 1280, FF_DIM, 1280, FF_PAD);
            add(uw + (size_t)l * 1280 * FF_DIM,
                guTh + (size_t)l * FF2 * 1280 + (size_t)FF_PAD * 1280,
                guTl + (size_t)l * FF2 * 1280 + (size_t)FF_PAD * 1280,
                1280, FF_DIM, 1280, FF_PAD);
            add(dw + (size_t)l * FF_DIM * 1280, downTh + (size_t)l * 1280 * FF_PAD,
                downTl + (size_t)l * 1280 * FF_PAD, FF_DIM, 1280, FF_PAD, 1280);
        }
        add(f1w, fc1Th, fc1Tl, 5120, 5120, 5120, 5120);
        add(f2w, fc2Th, fc2Tl, 5120, 3584, 5120, 3584);
        conv_all<<<tc, dim3(32, 8)>>>(tb);
    }

    const size_t psD = (size_t)T_TOK * D_MODEL;
    const size_t psQ = (size_t)T_TOK * 3 * D_MODEL;
    const size_t psF = (size_t)512 * 5120;
    const int n4F = 512 * 5120 / 4;

    // ---- patch embed: split-K4 + fused reduce/rmsnorm(n1 layer0) ----
    gemm_part<<<dim3(16, 10, 4), 256, GEMM_SMEM>>>(
        xh, xl, patchTh, patchTl, part, psD, PATCH_KP, 1280);
    reduce_rms<false><<<T_TOK, 256>>>(part, psD, 4, nullptr, n1s, h, nh, nl);

    for (int l = 0; l < DEPTH; l++) {
        const size_t lD = (size_t)l * D_MODEL;
        // qkv: split-K2; reduction fused into attention
        gemm_part<<<dim3(16, 30, 2), 256, GEMM_SMEM>>>(
            nh, nl, qkvTh + (size_t)l * 3840 * 1280, qkvTl + (size_t)l * 3840 * 1280,
            part, psQ, 1280, 3840);
        attn_kernel<<<dim3(NWIN, H_HEADS), 256, ATT_SMEM>>>(
            part, psQ, qkvb + (size_t)l * 3840, rot, ath, atl);
        // proj: split-K4, then fused reduce+res+rmsnorm(n2)
        gemm_part<<<dim3(16, 10, 4), 256, GEMM_SMEM>>>(
            ath, atl, projTh + (size_t)l * 1280 * 1280, projTl + (size_t)l * 1280 * 1280,
            part, psD, 1280, 1280);
        reduce_rms<true><<<T_TOK, 256>>>(part, psD, 4, projb + lD, n2s + lD, h, nh, nl);
        // fused gate|up GEMM
        gemm_bias<<<dim3(16, FF2 / 128), 256, GEMM_SMEM>>>(
            nh, nl, guTh + (size_t)l * FF2 * 1280, guTl + (size_t)l * FF2 * 1280,
            gub + (size_t)l * FF2, gu, 1280, FF2);
        silu_mul_quant<<<T_TOK, 256>>>(gu, uph, upl);
        // down: split-K4, then fused reduce+res+rmsnorm(next n1 or lnq)
        gemm_part<<<dim3(16, 10, 4), 256, GEMM_SMEM>>>(
            uph, upl, downTh + (size_t)l * 1280 * FF_PAD, downTl + (size_t)l * 1280 * FF_PAD,
            part, psD, FF_PAD, 1280);
        const float* nexts = (l < DEPTH - 1) ? (n1s + (size_t)(l + 1) * D_MODEL) : lnq;
        reduce_rms<true><<<T_TOK, 256>>>(part, psD, 4, db + lD, nexts, h, nh, nl);
    }

    // ---- merger (nh/nl viewed as [512, 5120]) ----
    gemm_part<<<dim3(4, 40, 8), 256, GEMM_SMEM>>>(
        nh, nl, fc1Th, fc1Tl, part, psF, 5120, 5120);
    reduce_gelu_pair<<<(n4F + 255) / 256, 256>>>(part, psF, 8, f1b, f1h, f1l, n4F, 5120);
    gemm_bias<<<dim3(4, 28), 256, GEMM_SMEM>>>(
        f1h, f1l, fc2Th, fc2Tl, f2b, out, 5120, 3584);
}